// round 10
// baseline (speedup 1.0000x reference)
#include <cuda_runtime.h>
#include <math.h>
#include <stdint.h>

#define BB 16
#define AA 65472
#define CC 81
#define GG 50
#define NBIN 2048
#define SH 20

__device__ float  g_best_iou[BB * AA];
__device__ int    g_best_idx[BB * AA];
__device__ int    g_labels[BB * AA];
__device__ float  g_mining[BB * AA];
__device__ float  g_cand[BB * AA];
__device__ unsigned long long g_gt_pack[BB * GG];
__device__ int    g_num_pos[BB];
__device__ int    g_ncand[BB];
__device__ unsigned int g_thr[BB];
__device__ int    g_r[BB];
__device__ double g_sumabove[BB];
__device__ double g_loc_sum;
__device__ double g_ce_sum;
__device__ unsigned int g_hist12[BB][NBIN];
__device__ int    g_ctr;

__device__ __forceinline__ float sl1_loss(float4 an, const float* __restrict__ gp, float4 p) {
    float acx = (an.x + an.z) * 0.5f, acy = (an.y + an.w) * 0.5f;
    float aw = an.z - an.x, ah = an.w - an.y;
    float mcx = (gp[0] + gp[2]) * 0.5f, mcy = (gp[1] + gp[3]) * 0.5f;
    float mw = gp[2] - gp[0], mh = gp[3] - gp[1];
    float t0 = (mcx - acx) / (aw * 0.1f);
    float t1 = (mcy - acy) / (ah * 0.1f);
    float t2 = logf(mw / aw + 1e-10f) * 5.0f;
    float t3 = logf(mh / ah + 1e-10f) * 5.0f;
    float n0 = fabsf(p.x - t0), n1 = fabsf(p.y - t1);
    float n2 = fabsf(p.z - t2), n3 = fabsf(p.w - t3);
    const float BETA = 1.0f / 9.0f;
    return (n0 < BETA ? 4.5f * n0 * n0 : n0 - 0.5f * BETA)
         + (n1 < BETA ? 4.5f * n1 * n1 : n1 - 0.5f * BETA)
         + (n2 < BETA ? 4.5f * n2 * n2 : n2 - 0.5f * BETA)
         + (n3 < BETA ? 4.5f * n3 * n3 : n3 - 0.5f * BETA);
}

__device__ __forceinline__ void cp_async16(float* dst, const float4* src) {
    unsigned sa = (unsigned)__cvta_generic_to_shared(dst);
    asm volatile("cp.async.cg.shared.global [%0], [%1], 16;" :: "r"(sa), "l"(src));
}

__global__ void k_init() {                       // 128 blocks x 256 threads
    int i = blockIdx.x * 256 + threadIdx.x;      // 32768 = BB*NBIN
    ((unsigned int*)g_hist12)[i] = 0u;
    if (i < BB * GG) g_gt_pack[i] = 0xFFFFFFFFull;
    if (i < BB) {
        g_num_pos[i] = 0; g_ncand[i] = 0; g_r[i] = 0;
        g_sumabove[i] = 0.0;
    }
    if (i == 0) { g_loc_sum = 0.0; g_ce_sum = 0.0; g_ctr = 0; }
}

// brute-force match (warp-uniform loop) + labels + loc loss + num_pos
__global__ void __launch_bounds__(256) k_match(const float* __restrict__ gts,
                                               const int* __restrict__ counts,
                                               const float* __restrict__ anchors,
                                               const float* __restrict__ pred) {
    int b = blockIdx.y;
    int a = blockIdx.x * 256 + threadIdx.x;
    __shared__ float4 sbox[GG];
    __shared__ float  sarea[GG];
    __shared__ float  slab[GG];
    __shared__ unsigned long long spack[GG];
    __shared__ double s_loc;
    __shared__ int s_np;
    int t = threadIdx.x;
    if (t < GG) {
        const float* gp = gts + ((size_t)b * GG + t) * 5;
        float4 bx = make_float4(gp[0], gp[1], gp[2], gp[3]);
        sbox[t] = bx;
        sarea[t] = (bx.z - bx.x) * (bx.w - bx.y) + 1e-10f;
        slab[t] = gp[4];
        spack[t] = 0ull;
    }
    if (t == 0) { s_loc = 0.0; s_np = 0; }
    __syncthreads();
    int count = counts[b];
    float lsum = 0.0f;
    int ispos = 0;
    if (a < AA) {
        float4 an = ((const float4*)anchors)[a];
        float areaA = (an.z - an.x) * (an.w - an.y);
        float best_q = 0.0f;
        int best_g = 0;
        unsigned int inva = 0xFFFFFFFFu - (unsigned int)a;
#pragma unroll 4
        for (int g = 0; g < count; g++) {
            float4 bx = sbox[g];
            float wx = fminf(an.z, bx.z) - fmaxf(an.x, bx.x);
            float wy = fminf(an.w, bx.w) - fmaxf(an.y, bx.y);
            wx = fmaxf(wx, 0.0f); wy = fmaxf(wy, 0.0f);
            float inter = wx * wy;
            float q = __fdividef(inter, areaA + sarea[g] - inter);
            if (q > best_q) { best_q = q; best_g = g; }       // first-max (asc g)
            if (inter > 0.0f) {
                unsigned long long pk =
                    (((unsigned long long)__float_as_uint(q)) << 32) | inva;
                if (pk > spack[g]) atomicMax(&spack[g], pk);  // racy read = filter
            }
        }
        size_t idx = (size_t)b * AA + a;
        g_best_iou[idx] = best_q;
        g_best_idx[idx] = best_g;
        int label = 0;
        if (best_q >= 0.5f) {
            label = (int)slab[best_g];
            ispos = 1;
            const float* gp = gts + ((size_t)b * GG + best_g) * 5;
            lsum = sl1_loss(an, gp, ((const float4*)pred)[idx]);
        }
        g_labels[idx] = label;
    }
    for (int o = 16; o; o >>= 1) {
        lsum  += __shfl_down_sync(0xffffffffu, lsum, o);
        ispos += __shfl_down_sync(0xffffffffu, ispos, o);
    }
    if ((threadIdx.x & 31) == 0 && ispos) {
        atomicAdd(&s_np, ispos);
        atomicAdd(&s_loc, (double)lsum);
    }
    __syncthreads();
    if (t == 0 && s_np) {
        atomicAdd(&g_num_pos[b], s_np);
        atomicAdd(&g_loc_sum, s_loc);
    }
    if (t < count && spack[t]) atomicMax(&g_gt_pack[b * GG + t], spack[t]);
}

__global__ void k_force(const float* __restrict__ gts,
                        const int* __restrict__ counts,
                        const float* __restrict__ anchors,
                        const float* __restrict__ pred) {
    int b = blockIdx.x;
    int j = threadIdx.x;
    __shared__ unsigned int sa[GG];
    int count = counts[b];
    unsigned int a = 0;
    if (j < count) {
        unsigned long long pk = g_gt_pack[b * GG + j];
        a = 0xFFFFFFFFu - (unsigned int)(pk & 0xFFFFFFFFull);
        sa[j] = a;
    }
    __syncthreads();
    if (j < count) {
        bool ok = true;                          // duplicate scatter: last j wins
        for (int j2 = j + 1; j2 < count; j2++)
            if (sa[j2] == a) ok = false;
        if (ok) {
            size_t idx = (size_t)b * AA + a;
            float q_old = g_best_iou[idx];
            int g_old = g_best_idx[idx];
            float4 an = ((const float4*)anchors)[a];
            float4 p = ((const float4*)pred)[idx];
            float loc_old = 0.0f;
            if (q_old >= 0.5f)
                loc_old = sl1_loss(an, gts + ((size_t)b * GG + g_old) * 5, p);
            else
                atomicAdd(&g_num_pos[b], 1);
            const float* gp = gts + ((size_t)b * GG + j) * 5;
            float loc_new = sl1_loss(an, gp, p);
            atomicAdd(&g_loc_sum, (double)loc_new - (double)loc_old);
            g_labels[idx] = (int)gp[4];
        }
    }
}

// cp.async double-buffered conf + fused 2-segment smem histogram
#define CROWS 128
#define CT 8
#define TILE_F (CROWS * CC)                      // 10368 floats
#define TILE_V (TILE_F / 4)
__global__ void __launch_bounds__(128) k_conf(const float* __restrict__ conf) {
    extern __shared__ float s[];                 // 2*TILE_F floats + 2*NBIN uints
    unsigned int* shh = (unsigned int*)(s + 2 * TILE_F);
    __shared__ double sce[4];
    int t = threadIdx.x;
    size_t tile0 = (size_t)blockIdx.x * CT;
    {   // prologue: async load tile 0 -> buf 0
        const float4* src = (const float4*)conf + tile0 * TILE_V;
        for (int i = t; i < TILE_V; i += 128) cp_async16(s + 4 * i, src + i);
        asm volatile("cp.async.commit_group;");
    }
#pragma unroll
    for (int i = t; i < 2 * NBIN; i += 128) shh[i] = 0;
    size_t row0 = tile0 * CROWS;
    int b0 = (int)(row0 / AA);
    size_t bsplit = (size_t)(b0 + 1) * AA;       // rows >= bsplit belong to b0+1
    double ce_acc = 0.0;
#pragma unroll
    for (int it = 0; it < CT; it++) {
        if (it + 1 < CT) {
            float* buf = s + ((it + 1) & 1) * TILE_F;
            const float4* src = (const float4*)conf + (tile0 + it + 1) * TILE_V;
            for (int i = t; i < TILE_V; i += 128) cp_async16(buf + 4 * i, src + i);
            asm volatile("cp.async.commit_group;");
            asm volatile("cp.async.wait_group 1;");
        } else {
            asm volatile("cp.async.wait_group 0;");
        }
        size_t row = (tile0 + it) * CROWS + t;
        int label = g_labels[row];
        __syncthreads();                         // tile visible (also orders hist zero)
        const float* rp = s + (it & 1) * TILE_F + t * CC;  // stride 81: conflict-free
        float e0 = 0.f, e1 = 0.f, e2 = 0.f, e3 = 0.f;
#pragma unroll
        for (int i = 0; i < 80; i += 4) {
            e0 += __expf(rp[i]);
            e1 += __expf(rp[i + 1]);
            e2 += __expf(rp[i + 2]);
            e3 += __expf(rp[i + 3]);
        }
        e0 += __expf(rp[80]);
        float lse = __logf((e0 + e1) + (e2 + e3));
        float m;
        if (label > 0) {
            ce_acc += (double)(lse - rp[label]);
            m = __int_as_float(0xff800000);      // -inf marker (bit31 set)
        } else {
            m = lse - rp[0];                     // > 0 always
            unsigned int u = __float_as_uint(m);
            int seg = (row >= bsplit) ? NBIN : 0;
            atomicAdd(&shh[seg + (u >> SH)], 1u);
        }
        g_mining[row] = m;
        __syncthreads();                         // buf reuse guard
    }
    float ce = (float)ce_acc;
    for (int o = 16; o; o >>= 1) ce += __shfl_down_sync(0xffffffffu, ce, o);
    if ((t & 31) == 0) sce[t >> 5] = (double)ce;
    __syncthreads();
    if (t == 0) {
        double tot = sce[0] + sce[1] + sce[2] + sce[3];
        if (tot != 0.0) atomicAdd(&g_ce_sum, tot);
    }
    // merge histograms (segment 0 -> b0, segment 1 -> b0+1)
#pragma unroll
    for (int i = t; i < NBIN; i += 128) {
        unsigned int c = shh[i];
        if (c) atomicAdd(&g_hist12[b0][i], c);
    }
    if (b0 + 1 < BB) {
#pragma unroll
        for (int i = t; i < NBIN; i += 128) {
            unsigned int c = shh[NBIN + i];
            if (c) atomicAdd(&g_hist12[b0 + 1][i], c);
        }
    }
}

// 512 blocks: redundant bin walk -> thr,r ; scan own chunk (sum above + compact);
// last finishing block: exact refinement for all batches + final output
__global__ void __launch_bounds__(256) k_collect(float* __restrict__ out) {
    __shared__ unsigned int scnt[256];
    __shared__ unsigned int s_thr;
    __shared__ int s_r;
    __shared__ double sred[8];
    __shared__ int s_last;
    __shared__ unsigned int hc[256];
    __shared__ double hsum[256];
    __shared__ unsigned int s_pref, s_pmask;
    __shared__ int s_r2;
    __shared__ double s_acc;
    int b = blockIdx.y;
    int t = threadIdx.x;
    int np = g_num_pos[b];
    long long kk = 3LL * np;
    int neg = AA - np;
    int k = (kk < (long long)neg) ? (int)kk : neg;
    {
        int lo = NBIN - (t + 1) * 8;             // descending 8-bin chunks
        unsigned int c = 0;
#pragma unroll
        for (int i = 0; i < 8; i++) c += g_hist12[b][lo + i];
        scnt[t] = c;
    }
    __syncthreads();
    if (t == 0) {
        if (k <= 0) { s_thr = 0xFFFFFFFFu; s_r = 0; }
        else {
            int cum = 0, j = 0;
            for (; j < 256; j++) {
                if (cum + (int)scnt[j] >= k) break;
                cum += (int)scnt[j];
            }
            int hi = NBIN - j * 8 - 1;
            int bin = hi, r = k - cum;
            for (int i = 0; i < 8; i++) {
                bin = hi - i;
                int cc = (int)g_hist12[b][bin];
                if (cum + cc >= k) { r = k - cum; break; }
                cum += cc;
            }
            s_thr = (unsigned int)bin; s_r = r;
        }
    }
    __syncthreads();
    unsigned int thr = s_thr;
    if ((int)thr >= 0) {                         // k > 0: do the scan
        if (blockIdx.x == 0 && t == 0) { g_thr[b] = thr; g_r[b] = s_r; }
        const int chunk = AA / 32;
        size_t base = (size_t)b * AA + (size_t)blockIdx.x * chunk;
        double acc = 0.0;
#pragma unroll 4
        for (int i = t; i < chunk; i += 256) {
            float v = g_mining[base + i];
            unsigned int u = __float_as_uint(v);
            if ((int)u >= 0) {
                unsigned int bin = u >> SH;
                if (bin > thr) acc += (double)v;
                else if (bin == thr) {
                    int slot = atomicAdd(&g_ncand[b], 1);
                    g_cand[(size_t)b * AA + slot] = v;
                }
            }
        }
        for (int o = 16; o; o >>= 1) acc += __shfl_down_sync(0xffffffffu, acc, o);
        if ((t & 31) == 0) sred[t >> 5] = acc;
        __syncthreads();
        if (t == 0) {
            double tot = 0.0;
            for (int i = 0; i < 8; i++) tot += sred[i];
            if (tot != 0.0) atomicAdd(&g_sumabove[b], tot);
        }
    }
    // last-block: exact top-k refinement + final combine
    __threadfence();
    if (t == 0) {
        int old = atomicAdd(&g_ctr, 1);
        s_last = (old == (int)(gridDim.x * gridDim.y) - 1);
    }
    __syncthreads();
    if (!s_last) return;

    double topk[BB];
    for (int bb = 0; bb < BB; bb++) {
        int r = g_r[bb];
        if (r == 0) { topk[bb] = g_sumabove[bb]; continue; }
        int n = g_ncand[bb];
        unsigned int thr2 = g_thr[bb];
        const float* cand = g_cand + (size_t)bb * AA;
        if (t == 0) { s_pref = 0u; s_pmask = 0u; s_r2 = r; s_acc = 0.0; }
        const int shifts[3] = {12, 4, 0};
        const int nbins[3]  = {256, 256, 16};
        for (int p = 0; p < 3; p++) {
            hc[t] = 0; hsum[t] = 0.0;
            __syncthreads();
            unsigned int pref = s_pref, pmask = s_pmask;
            int sh = shifts[p];
            unsigned int wmask = (unsigned)(nbins[p] - 1);
            for (int i = t; i < n; i += 256) {
                float v = cand[i];
                unsigned int u = __float_as_uint(v);
                if ((u & pmask) == pref) {
                    unsigned int idx = (u >> sh) & wmask;
                    atomicAdd(&hc[idx], 1u);
                    atomicAdd(&hsum[idx], (double)v);
                }
            }
            __syncthreads();
            if (t == 0) {
                int rr = s_r2, cum = 0; double sa = 0.0; int bin = nbins[p] - 1;
                for (bin = nbins[p] - 1; bin >= 0; bin--) {
                    int cc = (int)hc[bin];
                    if (cum + cc >= rr) break;
                    cum += cc; sa += hsum[bin];
                }
                s_acc += sa;
                s_r2 = rr - cum;
                s_pref |= (unsigned)bin << sh;
                s_pmask |= wmask << sh;
            }
            __syncthreads();
        }
        unsigned int fb = (thr2 << SH) | s_pref;    // exact tie value
        topk[bb] = g_sumabove[bb] + s_acc + (double)s_r2 * (double)__uint_as_float(fb);
        __syncthreads();
    }
    if (t == 0) {
        long long npt = 0;
        double tk = 0.0;
        for (int bb = 0; bb < BB; bb++) { npt += g_num_pos[bb]; tk += topk[bb]; }
        double num_pos = (npt < 1) ? 1.0 : (double)npt;
        double inv = 1.0 / (num_pos * 4.0);
        out[0] = (float)(g_loc_sum * inv);
        out[1] = (float)((g_ce_sum + tk) * inv);
    }
}

extern "C" void kernel_launch(void* const* d_in, const int* in_sizes, int n_in,
                              void* d_out, int out_size) {
    const float* conf    = (const float*)d_in[0];
    const float* pred    = (const float*)d_in[1];
    const float* gts     = (const float*)d_in[2];
    const int*   counts  = (const int*)  d_in[3];
    const float* anchors = (const float*)d_in[4];
    float* out = (float*)d_out;

    static int attr_set = 0;
    if (!attr_set) {
        cudaFuncSetAttribute(k_conf, cudaFuncAttributeMaxDynamicSharedMemorySize,
                             2 * TILE_F * sizeof(float) + 2 * NBIN * sizeof(unsigned int));
        attr_set = 1;
    }

    k_init<<<BB * NBIN / 256, 256>>>();
    dim3 gm((AA + 255) / 256, BB);
    k_match<<<gm, 256>>>(gts, counts, anchors, pred);
    k_force<<<BB, GG>>>(gts, counts, anchors, pred);
    k_conf<<<(BB * AA) / (CROWS * CT), 128,
             2 * TILE_F * sizeof(float) + 2 * NBIN * sizeof(unsigned int)>>>(conf);
    k_collect<<<dim3(32, BB), 256>>>(out);
}

// round 11
// speedup vs baseline: 4.2089x; 4.2089x over previous
#include <cuda_runtime.h>
#include <math.h>
#include <stdint.h>

#define BB 16
#define AA 65472
#define CC 81
#define GG 50
#define NBIN 4096
#define SH 19

__device__ float  g_best_iou[BB * AA];
__device__ int    g_best_idx[BB * AA];
__device__ int    g_labels[BB * AA];
__device__ float  g_mining[BB * AA];
__device__ float  g_cand[BB * AA];
__device__ unsigned long long g_gt_pack[BB * GG];
__device__ int    g_num_pos[BB];
__device__ int    g_ncand[BB];
__device__ unsigned int g_thr[BB];
__device__ int    g_r[BB];
__device__ double g_sumabove[BB];
__device__ double g_topk_sum[BB];
__device__ double g_loc_sum;
__device__ double g_ce_sum;
__device__ unsigned int g_hist12[BB][NBIN];

__device__ __forceinline__ float sl1_loss(float4 an, const float* __restrict__ gp, float4 p) {
    float acx = (an.x + an.z) * 0.5f, acy = (an.y + an.w) * 0.5f;
    float aw = an.z - an.x, ah = an.w - an.y;
    float mcx = (gp[0] + gp[2]) * 0.5f, mcy = (gp[1] + gp[3]) * 0.5f;
    float mw = gp[2] - gp[0], mh = gp[3] - gp[1];
    float t0 = (mcx - acx) / (aw * 0.1f);
    float t1 = (mcy - acy) / (ah * 0.1f);
    float t2 = logf(mw / aw + 1e-10f) * 5.0f;
    float t3 = logf(mh / ah + 1e-10f) * 5.0f;
    float n0 = fabsf(p.x - t0), n1 = fabsf(p.y - t1);
    float n2 = fabsf(p.z - t2), n3 = fabsf(p.w - t3);
    const float BETA = 1.0f / 9.0f;
    return (n0 < BETA ? 4.5f * n0 * n0 : n0 - 0.5f * BETA)
         + (n1 < BETA ? 4.5f * n1 * n1 : n1 - 0.5f * BETA)
         + (n2 < BETA ? 4.5f * n2 * n2 : n2 - 0.5f * BETA)
         + (n3 < BETA ? 4.5f * n3 * n3 : n3 - 0.5f * BETA);
}

__device__ __forceinline__ void cp_async16(float* dst, const float4* src) {
    unsigned sa = (unsigned)__cvta_generic_to_shared(dst);
    asm volatile("cp.async.cg.shared.global [%0], [%1], 16;" :: "r"(sa), "l"(src));
}

__global__ void k_init() {                       // 256 blocks x 256 threads
    int i = blockIdx.x * 256 + threadIdx.x;      // 65536 = BB*NBIN
    ((unsigned int*)g_hist12)[i] = 0u;
    if (i < BB * GG) g_gt_pack[i] = 0xFFFFFFFFull;   // iou=0, anchor 0 default
    if (i < BB) {
        g_num_pos[i] = 0; g_ncand[i] = 0; g_r[i] = 0;
        g_topk_sum[i] = 0.0; g_sumabove[i] = 0.0;
    }
    if (i == 0) { g_loc_sum = 0.0; g_ce_sum = 0.0; }
}

// brute-force match (warp-uniform loop) + labels + loc loss + num_pos
__global__ void __launch_bounds__(256) k_match(const float* __restrict__ gts,
                                               const int* __restrict__ counts,
                                               const float* __restrict__ anchors,
                                               const float* __restrict__ pred) {
    int b = blockIdx.y;
    int a = blockIdx.x * 256 + threadIdx.x;
    __shared__ float4 sbox[GG];
    __shared__ float  sarea[GG];
    __shared__ float  slab[GG];
    __shared__ unsigned long long spack[GG];
    __shared__ double s_loc;
    __shared__ int s_np;
    int t = threadIdx.x;
    if (t < GG) {
        const float* gp = gts + ((size_t)b * GG + t) * 5;
        float4 bx = make_float4(gp[0], gp[1], gp[2], gp[3]);
        sbox[t] = bx;
        sarea[t] = (bx.z - bx.x) * (bx.w - bx.y) + 1e-10f;
        slab[t] = gp[4];
        spack[t] = 0ull;
    }
    if (t == 0) { s_loc = 0.0; s_np = 0; }
    __syncthreads();
    int count = counts[b];
    float lsum = 0.0f;
    int ispos = 0;
    if (a < AA) {
        float4 an = ((const float4*)anchors)[a];
        float areaA = (an.z - an.x) * (an.w - an.y);
        float best_q = 0.0f;
        int best_g = 0;
        unsigned int inva = 0xFFFFFFFFu - (unsigned int)a;
#pragma unroll 4
        for (int g = 0; g < count; g++) {
            float4 bx = sbox[g];
            float wx = fminf(an.z, bx.z) - fmaxf(an.x, bx.x);
            float wy = fminf(an.w, bx.w) - fmaxf(an.y, bx.y);
            wx = fmaxf(wx, 0.0f); wy = fmaxf(wy, 0.0f);
            float inter = wx * wy;
            float q = __fdividef(inter, areaA + sarea[g] - inter);
            if (q > best_q) { best_q = q; best_g = g; }       // first-max (asc g)
            if (inter > 0.0f) {
                unsigned long long pk =
                    (((unsigned long long)__float_as_uint(q)) << 32) | inva;
                if (pk > spack[g]) atomicMax(&spack[g], pk);  // racy read = filter
            }
        }
        size_t idx = (size_t)b * AA + a;
        g_best_iou[idx] = best_q;
        g_best_idx[idx] = best_g;
        int label = 0;
        if (best_q >= 0.5f) {
            label = (int)slab[best_g];
            ispos = 1;
            const float* gp = gts + ((size_t)b * GG + best_g) * 5;
            lsum = sl1_loss(an, gp, ((const float4*)pred)[idx]);
        }
        g_labels[idx] = label;
    }
    for (int o = 16; o; o >>= 1) {
        lsum  += __shfl_down_sync(0xffffffffu, lsum, o);
        ispos += __shfl_down_sync(0xffffffffu, ispos, o);
    }
    if ((threadIdx.x & 31) == 0 && ispos) {
        atomicAdd(&s_np, ispos);
        atomicAdd(&s_loc, (double)lsum);
    }
    __syncthreads();
    if (t == 0 && s_np) {
        atomicAdd(&g_num_pos[b], s_np);
        atomicAdd(&g_loc_sum, s_loc);
    }
    if (t < count && spack[t]) atomicMax(&g_gt_pack[b * GG + t], spack[t]);
}

__global__ void k_force(const float* __restrict__ gts,
                        const int* __restrict__ counts,
                        const float* __restrict__ anchors,
                        const float* __restrict__ pred) {
    int b = blockIdx.x;
    int j = threadIdx.x;
    __shared__ unsigned int sa[GG];
    int count = counts[b];
    unsigned int a = 0;
    if (j < count) {
        unsigned long long pk = g_gt_pack[b * GG + j];
        a = 0xFFFFFFFFu - (unsigned int)(pk & 0xFFFFFFFFull);
        sa[j] = a;
    }
    __syncthreads();
    if (j < count) {
        bool ok = true;                          // duplicate scatter: last j wins
        for (int j2 = j + 1; j2 < count; j2++)
            if (sa[j2] == a) ok = false;
        if (ok) {
            size_t idx = (size_t)b * AA + a;
            float q_old = g_best_iou[idx];
            int g_old = g_best_idx[idx];
            float4 an = ((const float4*)anchors)[a];
            float4 p = ((const float4*)pred)[idx];
            float loc_old = 0.0f;
            if (q_old >= 0.5f)
                loc_old = sl1_loss(an, gts + ((size_t)b * GG + g_old) * 5, p);
            else
                atomicAdd(&g_num_pos[b], 1);
            const float* gp = gts + ((size_t)b * GG + j) * 5;
            float loc_new = sl1_loss(an, gp, p);
            atomicAdd(&g_loc_sum, (double)loc_new - (double)loc_old);
            g_labels[idx] = (int)gp[4];
        }
    }
}

// cp.async double-buffered: 64 threads, 8 tiles of 64 rows per block
#define CROWS 64
#define CT 8
#define TILE_F (CROWS * CC)                      // 5184 floats = 20736 B
#define TILE_V (TILE_F / 4)                      // 1296 float4
__global__ void __launch_bounds__(64) k_conf(const float* __restrict__ conf) {
    extern __shared__ float s[];                 // 2 * TILE_F floats = 41472 B
    __shared__ double sce[2];
    int t = threadIdx.x;
    size_t tile0 = (size_t)blockIdx.x * CT;
    {   // prologue: async load tile 0 -> buf 0
        const float4* src = (const float4*)conf + tile0 * TILE_V;
        for (int i = t; i < TILE_V; i += 64) cp_async16(s + 4 * i, src + i);
        asm volatile("cp.async.commit_group;");
    }
    double ce_acc = 0.0;
#pragma unroll
    for (int it = 0; it < CT; it++) {
        if (it + 1 < CT) {                       // prefetch next tile
            float* buf = s + ((it + 1) & 1) * TILE_F;
            const float4* src = (const float4*)conf + (tile0 + it + 1) * TILE_V;
            for (int i = t; i < TILE_V; i += 64) cp_async16(buf + 4 * i, src + i);
            asm volatile("cp.async.commit_group;");
            asm volatile("cp.async.wait_group 1;");
        } else {
            asm volatile("cp.async.wait_group 0;");
        }
        size_t rowbase = (tile0 + it) * CROWS;
        int label = g_labels[rowbase + t];
        __syncthreads();                         // tile 'it' visible to all
        const float* row = s + (it & 1) * TILE_F + t * CC;   // stride 81: conflict-free
        float e0 = 0.f, e1 = 0.f, e2 = 0.f, e3 = 0.f;
#pragma unroll
        for (int i = 0; i < 80; i += 4) {
            e0 += __expf(row[i]);
            e1 += __expf(row[i + 1]);
            e2 += __expf(row[i + 2]);
            e3 += __expf(row[i + 3]);
        }
        e0 += __expf(row[80]);
        float lse = __logf((e0 + e1) + (e2 + e3));
        float m;
        if (label > 0) {
            ce_acc += (double)(lse - row[label]);
            m = __int_as_float(0xff800000);      // -inf marker (bit31 set)
        } else {
            m = lse - row[0];                    // > 0 always
        }
        g_mining[rowbase + t] = m;
        __syncthreads();                         // done reading buf before reuse
    }
    float ce = (float)ce_acc;
    for (int o = 16; o; o >>= 1) ce += __shfl_down_sync(0xffffffffu, ce, o);
    if ((t & 31) == 0) sce[t >> 5] = (double)ce;
    __syncthreads();
    if (t == 0) {
        double tot = sce[0] + sce[1];
        if (tot != 0.0) atomicAdd(&g_ce_sum, tot);
    }
}

// distributed 12-bit histogram: 512 blocks, 16KB private smem
__global__ void __launch_bounds__(256) k_hist() {
    __shared__ unsigned int sh[NBIN];
    int b = blockIdx.y;
#pragma unroll
    for (int i = threadIdx.x; i < NBIN; i += 256) sh[i] = 0;
    __syncthreads();
    const int chunk = AA / 32;                   // 2046 exact
    size_t base = (size_t)b * AA + (size_t)blockIdx.x * chunk;
#pragma unroll 4
    for (int i = threadIdx.x; i < chunk; i += 256) {
        unsigned int u = __float_as_uint(g_mining[base + i]);
        if ((int)u >= 0) atomicAdd(&sh[u >> SH], 1u);
    }
    __syncthreads();
#pragma unroll
    for (int i = threadIdx.x; i < NBIN; i += 256) {
        unsigned int c = sh[i];
        if (c) atomicAdd(&g_hist12[b][i], c);
    }
}

// 512 blocks: redundant bin walk -> thr,r ; scan own chunk
__global__ void __launch_bounds__(256) k_collect() {
    __shared__ unsigned int scnt[256];
    __shared__ unsigned int s_thr;
    __shared__ int s_r;
    __shared__ double sred[8];
    int b = blockIdx.y;
    int t = threadIdx.x;
    int np = g_num_pos[b];
    long long kk = 3LL * np;
    int neg = AA - np;
    int k = (kk < (long long)neg) ? (int)kk : neg;
    {
        int lo = NBIN - (t + 1) * 16;            // descending 16-bin chunks
        unsigned int c = 0;
#pragma unroll
        for (int i = 0; i < 16; i++) c += g_hist12[b][lo + i];
        scnt[t] = c;
    }
    __syncthreads();
    if (t == 0) {
        if (k <= 0) { s_thr = 0xFFFFFFFFu; s_r = 0; }
        else {
            int cum = 0, j = 0;
            for (; j < 256; j++) {
                if (cum + (int)scnt[j] >= k) break;
                cum += (int)scnt[j];
            }
            int hi = NBIN - j * 16 - 1;
            int bin = hi, r = k - cum;
            for (int i = 0; i < 16; i++) {
                bin = hi - i;
                int cc = (int)g_hist12[b][bin];
                if (cum + cc >= k) { r = k - cum; break; }
                cum += cc;
            }
            s_thr = (unsigned int)bin; s_r = r;
        }
    }
    __syncthreads();
    unsigned int thr = s_thr;
    if ((int)thr < 0) return;                    // k<=0: topk stays 0
    if (blockIdx.x == 0 && t == 0) { g_thr[b] = thr; g_r[b] = s_r; }
    const int chunk = AA / 32;
    size_t base = (size_t)b * AA + (size_t)blockIdx.x * chunk;
    double acc = 0.0;
#pragma unroll 4
    for (int i = t; i < chunk; i += 256) {
        float v = g_mining[base + i];
        unsigned int u = __float_as_uint(v);
        if ((int)u >= 0) {
            unsigned int bin = u >> SH;
            if (bin > thr) acc += (double)v;
            else if (bin == thr) {
                int slot = atomicAdd(&g_ncand[b], 1);
                g_cand[(size_t)b * AA + slot] = v;
            }
        }
    }
    for (int o = 16; o; o >>= 1) acc += __shfl_down_sync(0xffffffffu, acc, o);
    if ((t & 31) == 0) sred[t >> 5] = acc;
    __syncthreads();
    if (t == 0) {
        double tot = 0.0;
        for (int i = 0; i < 8; i++) tot += sred[i];
        if (tot != 0.0) atomicAdd(&g_sumabove[b], tot);
    }
}

// exact refinement over thr-bin candidates: 3 passes on bits [18:11],[10:3],[2:0]
__global__ void __launch_bounds__(256) k_sel2() {
    int b = blockIdx.x;
    int r = g_r[b];
    if (r == 0) { if (threadIdx.x == 0) g_topk_sum[b] = g_sumabove[b]; return; }
    int n = g_ncand[b];
    unsigned int thr = g_thr[b];
    __shared__ unsigned int hc[256];
    __shared__ double hsum[256];
    __shared__ unsigned int s_pref, s_pmask;
    __shared__ int s_r2;
    __shared__ double s_acc;
    const float* cand = g_cand + (size_t)b * AA;
    if (threadIdx.x == 0) { s_pref = 0u; s_pmask = 0u; s_r2 = r; s_acc = 0.0; }
    const int shifts[3] = {11, 3, 0};
    const int nbins[3]  = {256, 256, 8};
    for (int p = 0; p < 3; p++) {
        hc[threadIdx.x] = 0; hsum[threadIdx.x] = 0.0;
        __syncthreads();
        unsigned int pref = s_pref, pmask = s_pmask;
        int sh = shifts[p];
        unsigned int wmask = (unsigned)(nbins[p] - 1);
        for (int i = threadIdx.x; i < n; i += 256) {
            float v = cand[i];
            unsigned int u = __float_as_uint(v);
            if ((u & pmask) == pref) {
                unsigned int idx = (u >> sh) & wmask;
                atomicAdd(&hc[idx], 1u);
                atomicAdd(&hsum[idx], (double)v);
            }
        }
        __syncthreads();
        if (threadIdx.x == 0) {
            int rr = s_r2, cum = 0; double sa = 0.0; int bin = nbins[p] - 1;
            for (bin = nbins[p] - 1; bin >= 0; bin--) {
                int cc = (int)hc[bin];
                if (cum + cc >= rr) break;
                cum += cc; sa += hsum[bin];
            }
            s_acc += sa;
            s_r2 = rr - cum;
            s_pref |= (unsigned)bin << sh;
            s_pmask |= wmask << sh;
        }
        __syncthreads();
    }
    if (threadIdx.x == 0) {
        unsigned int fb = (thr << SH) | s_pref;  // exact tie value
        g_topk_sum[b] = g_sumabove[b] + s_acc + (double)s_r2 * (double)__uint_as_float(fb);
    }
}

__global__ void k_final(float* __restrict__ out) {
    long long np = 0;
    double tk = 0.0;
    for (int b = 0; b < BB; b++) { np += g_num_pos[b]; tk += g_topk_sum[b]; }
    double num_pos = (np < 1) ? 1.0 : (double)np;
    double inv = 1.0 / (num_pos * 4.0);
    out[0] = (float)(g_loc_sum * inv);
    out[1] = (float)((g_ce_sum + tk) * inv);
}

extern "C" void kernel_launch(void* const* d_in, const int* in_sizes, int n_in,
                              void* d_out, int out_size) {
    const float* conf    = (const float*)d_in[0];
    const float* pred    = (const float*)d_in[1];
    const float* gts     = (const float*)d_in[2];
    const int*   counts  = (const int*)  d_in[3];
    const float* anchors = (const float*)d_in[4];
    float* out = (float*)d_out;

    static int attr_set = 0;
    if (!attr_set) {
        cudaFuncSetAttribute(k_conf, cudaFuncAttributeMaxDynamicSharedMemorySize,
                             2 * TILE_F * sizeof(float));
        attr_set = 1;
    }

    k_init<<<BB * NBIN / 256, 256>>>();
    dim3 gm((AA + 255) / 256, BB);
    k_match<<<gm, 256>>>(gts, counts, anchors, pred);
    k_force<<<BB, GG>>>(gts, counts, anchors, pred);
    k_conf<<<(BB * AA) / (CROWS * CT), 64, 2 * TILE_F * sizeof(float)>>>(conf);  // #4 profiled
    k_hist<<<dim3(32, BB), 256>>>();
    k_collect<<<dim3(32, BB), 256>>>();
    k_sel2<<<BB, 256>>>();
    k_final<<<1, 1>>>(out);
}

// round 12
// speedup vs baseline: 4.2096x; 1.0002x over previous
#include <cuda_runtime.h>
#include <math.h>
#include <stdint.h>

#define BB 16
#define AA 65472
#define CC 81
#define GG 50
#define NBIN 4096
#define SH 19

__device__ float  g_best_iou[BB * AA];
__device__ int    g_best_idx[BB * AA];
__device__ int    g_labels[BB * AA];
__device__ float  g_mining[BB * AA];
__device__ float  g_cand[BB * AA];
__device__ unsigned long long g_gt_pack[BB * GG];
__device__ int    g_num_pos[BB];
__device__ int    g_ncand[BB];
__device__ unsigned int g_thr[BB];
__device__ int    g_r[BB];
__device__ double g_sumabove[BB];
__device__ double g_topk_sum[BB];
__device__ double g_loc_sum;
__device__ double g_ce_sum;
__device__ unsigned int g_hist12[BB][NBIN];
__device__ int    g_ctr;

__device__ __forceinline__ float sl1_loss(float4 an, const float* __restrict__ gp, float4 p) {
    float acx = (an.x + an.z) * 0.5f, acy = (an.y + an.w) * 0.5f;
    float aw = an.z - an.x, ah = an.w - an.y;
    float mcx = (gp[0] + gp[2]) * 0.5f, mcy = (gp[1] + gp[3]) * 0.5f;
    float mw = gp[2] - gp[0], mh = gp[3] - gp[1];
    float t0 = (mcx - acx) / (aw * 0.1f);
    float t1 = (mcy - acy) / (ah * 0.1f);
    float t2 = logf(mw / aw + 1e-10f) * 5.0f;
    float t3 = logf(mh / ah + 1e-10f) * 5.0f;
    float n0 = fabsf(p.x - t0), n1 = fabsf(p.y - t1);
    float n2 = fabsf(p.z - t2), n3 = fabsf(p.w - t3);
    const float BETA = 1.0f / 9.0f;
    return (n0 < BETA ? 4.5f * n0 * n0 : n0 - 0.5f * BETA)
         + (n1 < BETA ? 4.5f * n1 * n1 : n1 - 0.5f * BETA)
         + (n2 < BETA ? 4.5f * n2 * n2 : n2 - 0.5f * BETA)
         + (n3 < BETA ? 4.5f * n3 * n3 : n3 - 0.5f * BETA);
}

__device__ __forceinline__ void cp_async16(float* dst, const float4* src) {
    unsigned sa = (unsigned)__cvta_generic_to_shared(dst);
    asm volatile("cp.async.cg.shared.global [%0], [%1], 16;" :: "r"(sa), "l"(src));
}

#define HIST_THIRD ((BB * NBIN) / 3 + 1)             // 21846

__global__ void k_init_a() {
    int i = blockIdx.x * 256 + threadIdx.x;
    if (i < HIST_THIRD) ((unsigned int*)g_hist12)[i] = 0u;
    if (i < BB * GG) g_gt_pack[i] = 0xFFFFFFFFull;   // iou=0, anchor 0 default
}
__global__ void k_init_b() {
    int i = blockIdx.x * 256 + threadIdx.x;
    int j = i + HIST_THIRD;
    if (j < BB * NBIN) ((unsigned int*)g_hist12)[j] = 0u;
    if (i < BB) {
        g_num_pos[i] = 0; g_ncand[i] = 0; g_r[i] = 0;
        g_topk_sum[i] = 0.0; g_sumabove[i] = 0.0;
    }
}
__global__ void k_init_c() {
    int i = blockIdx.x * 256 + threadIdx.x;
    int j = i + 2 * HIST_THIRD;
    if (j < BB * NBIN) ((unsigned int*)g_hist12)[j] = 0u;
    if (i == 0) { g_loc_sum = 0.0; g_ce_sum = 0.0; g_ctr = 0; }
}

// brute-force match (warp-uniform loop) + labels + loc loss + num_pos
__global__ void __launch_bounds__(256) k_match(const float* __restrict__ gts,
                                               const int* __restrict__ counts,
                                               const float* __restrict__ anchors,
                                               const float* __restrict__ pred) {
    int b = blockIdx.y;
    int a = blockIdx.x * 256 + threadIdx.x;
    __shared__ float4 sbox[GG];
    __shared__ float  sarea[GG];
    __shared__ float  slab[GG];
    __shared__ unsigned long long spack[GG];
    __shared__ double s_loc;
    __shared__ int s_np;
    int t = threadIdx.x;
    if (t < GG) {
        const float* gp = gts + ((size_t)b * GG + t) * 5;
        float4 bx = make_float4(gp[0], gp[1], gp[2], gp[3]);
        sbox[t] = bx;
        sarea[t] = (bx.z - bx.x) * (bx.w - bx.y) + 1e-10f;
        slab[t] = gp[4];
        spack[t] = 0ull;
    }
    if (t == 0) { s_loc = 0.0; s_np = 0; }
    __syncthreads();
    int count = counts[b];
    float lsum = 0.0f;
    int ispos = 0;
    if (a < AA) {
        float4 an = ((const float4*)anchors)[a];
        float areaA = (an.z - an.x) * (an.w - an.y);
        float best_q = 0.0f;
        int best_g = 0;
        unsigned int inva = 0xFFFFFFFFu - (unsigned int)a;
#pragma unroll 4
        for (int g = 0; g < count; g++) {
            float4 bx = sbox[g];
            float wx = fminf(an.z, bx.z) - fmaxf(an.x, bx.x);
            float wy = fminf(an.w, bx.w) - fmaxf(an.y, bx.y);
            wx = fmaxf(wx, 0.0f); wy = fmaxf(wy, 0.0f);
            float inter = wx * wy;
            float q = __fdividef(inter, areaA + sarea[g] - inter);
            if (q > best_q) { best_q = q; best_g = g; }       // first-max (asc g)
            if (inter > 0.0f) {
                unsigned long long pk =
                    (((unsigned long long)__float_as_uint(q)) << 32) | inva;
                if (pk > spack[g]) atomicMax(&spack[g], pk);  // racy read = filter
            }
        }
        size_t idx = (size_t)b * AA + a;
        g_best_iou[idx] = best_q;
        g_best_idx[idx] = best_g;
        int label = 0;
        if (best_q >= 0.5f) {
            label = (int)slab[best_g];
            ispos = 1;
            const float* gp = gts + ((size_t)b * GG + best_g) * 5;
            lsum = sl1_loss(an, gp, ((const float4*)pred)[idx]);
        }
        g_labels[idx] = label;
    }
    for (int o = 16; o; o >>= 1) {
        lsum  += __shfl_down_sync(0xffffffffu, lsum, o);
        ispos += __shfl_down_sync(0xffffffffu, ispos, o);
    }
    if ((threadIdx.x & 31) == 0 && ispos) {
        atomicAdd(&s_np, ispos);
        atomicAdd(&s_loc, (double)lsum);
    }
    __syncthreads();
    if (t == 0 && s_np) {
        atomicAdd(&g_num_pos[b], s_np);
        atomicAdd(&g_loc_sum, s_loc);
    }
    if (t < count && spack[t]) atomicMax(&g_gt_pack[b * GG + t], spack[t]);
}

__global__ void k_force(const float* __restrict__ gts,
                        const int* __restrict__ counts,
                        const float* __restrict__ anchors,
                        const float* __restrict__ pred) {
    int b = blockIdx.x;
    int j = threadIdx.x;
    __shared__ unsigned int sa[GG];
    int count = counts[b];
    unsigned int a = 0;
    if (j < count) {
        unsigned long long pk = g_gt_pack[b * GG + j];
        a = 0xFFFFFFFFu - (unsigned int)(pk & 0xFFFFFFFFull);
        sa[j] = a;
    }
    __syncthreads();
    if (j < count) {
        bool ok = true;                          // duplicate scatter: last j wins
        for (int j2 = j + 1; j2 < count; j2++)
            if (sa[j2] == a) ok = false;
        if (ok) {
            size_t idx = (size_t)b * AA + a;
            float q_old = g_best_iou[idx];
            int g_old = g_best_idx[idx];
            float4 an = ((const float4*)anchors)[a];
            float4 p = ((const float4*)pred)[idx];
            float loc_old = 0.0f;
            if (q_old >= 0.5f)
                loc_old = sl1_loss(an, gts + ((size_t)b * GG + g_old) * 5, p);
            else
                atomicAdd(&g_num_pos[b], 1);
            const float* gp = gts + ((size_t)b * GG + j) * 5;
            float loc_new = sl1_loss(an, gp, p);
            atomicAdd(&g_loc_sum, (double)loc_new - (double)loc_old);
            g_labels[idx] = (int)gp[4];
        }
    }
}

// cp.async double-buffered: 128 threads, 4 tiles of 128 rows per block (R8 shape)
#define CROWS 128
#define CT 4
#define TILE_F (CROWS * CC)                      // 10368 floats
#define TILE_V (TILE_F / 4)                      // 2592 float4
__global__ void __launch_bounds__(128) k_conf(const float* __restrict__ conf) {
    extern __shared__ float s[];                 // 2 * TILE_F floats = 82944 B
    __shared__ double sce[4];
    int t = threadIdx.x;
    size_t tile0 = (size_t)blockIdx.x * CT;
    {   // prologue: async load tile 0 -> buf 0
        const float4* src = (const float4*)conf + tile0 * TILE_V;
        for (int i = t; i < TILE_V; i += 128) cp_async16(s + 4 * i, src + i);
        asm volatile("cp.async.commit_group;");
    }
    double ce_acc = 0.0;
#pragma unroll
    for (int it = 0; it < CT; it++) {
        if (it + 1 < CT) {                       // prefetch next tile
            float* buf = s + ((it + 1) & 1) * TILE_F;
            const float4* src = (const float4*)conf + (tile0 + it + 1) * TILE_V;
            for (int i = t; i < TILE_V; i += 128) cp_async16(buf + 4 * i, src + i);
            asm volatile("cp.async.commit_group;");
            asm volatile("cp.async.wait_group 1;");
        } else {
            asm volatile("cp.async.wait_group 0;");
        }
        size_t rowbase = (tile0 + it) * CROWS;
        int label = g_labels[rowbase + t];
        __syncthreads();                         // tile 'it' visible to all
        const float* row = s + (it & 1) * TILE_F + t * CC;   // stride 81: conflict-free
        float e0 = 0.f, e1 = 0.f, e2 = 0.f, e3 = 0.f;
#pragma unroll
        for (int i = 0; i < 80; i += 4) {
            e0 += __expf(row[i]);
            e1 += __expf(row[i + 1]);
            e2 += __expf(row[i + 2]);
            e3 += __expf(row[i + 3]);
        }
        e0 += __expf(row[80]);
        float lse = __logf((e0 + e1) + (e2 + e3));
        float m;
        if (label > 0) {
            ce_acc += (double)(lse - row[label]);
            m = __int_as_float(0xff800000);      // -inf marker (bit31 set)
        } else {
            m = lse - row[0];                    // > 0 always
        }
        g_mining[rowbase + t] = m;
        __syncthreads();                         // done reading buf before reuse
    }
    float ce = (float)ce_acc;
    for (int o = 16; o; o >>= 1) ce += __shfl_down_sync(0xffffffffu, ce, o);
    if ((t & 31) == 0) sce[t >> 5] = (double)ce;
    __syncthreads();
    if (t == 0) {
        double tot = sce[0] + sce[1] + sce[2] + sce[3];
        if (tot != 0.0) atomicAdd(&g_ce_sum, tot);
    }
}

// distributed 12-bit histogram: 512 blocks, 16KB private smem
__global__ void __launch_bounds__(256) k_hist() {
    __shared__ unsigned int sh[NBIN];
    int b = blockIdx.y;
#pragma unroll
    for (int i = threadIdx.x; i < NBIN; i += 256) sh[i] = 0;
    __syncthreads();
    const int chunk = AA / 32;                   // 2046 exact
    size_t base = (size_t)b * AA + (size_t)blockIdx.x * chunk;
#pragma unroll 4
    for (int i = threadIdx.x; i < chunk; i += 256) {
        unsigned int u = __float_as_uint(g_mining[base + i]);
        if ((int)u >= 0) atomicAdd(&sh[u >> SH], 1u);
    }
    __syncthreads();
#pragma unroll
    for (int i = threadIdx.x; i < NBIN; i += 256) {
        unsigned int c = sh[i];
        if (c) atomicAdd(&g_hist12[b][i], c);
    }
}

// 512 blocks: redundant bin walk -> thr,r ; scan own chunk
__global__ void __launch_bounds__(256) k_collect() {
    __shared__ unsigned int scnt[256];
    __shared__ unsigned int s_thr;
    __shared__ int s_r;
    __shared__ double sred[8];
    int b = blockIdx.y;
    int t = threadIdx.x;
    int np = g_num_pos[b];
    long long kk = 3LL * np;
    int neg = AA - np;
    int k = (kk < (long long)neg) ? (int)kk : neg;
    {
        int lo = NBIN - (t + 1) * 16;            // descending 16-bin chunks
        unsigned int c = 0;
#pragma unroll
        for (int i = 0; i < 16; i++) c += g_hist12[b][lo + i];
        scnt[t] = c;
    }
    __syncthreads();
    if (t == 0) {
        if (k <= 0) { s_thr = 0xFFFFFFFFu; s_r = 0; }
        else {
            int cum = 0, j = 0;
            for (; j < 256; j++) {
                if (cum + (int)scnt[j] >= k) break;
                cum += (int)scnt[j];
            }
            int hi = NBIN - j * 16 - 1;
            int bin = hi, r = k - cum;
            for (int i = 0; i < 16; i++) {
                bin = hi - i;
                int cc = (int)g_hist12[b][bin];
                if (cum + cc >= k) { r = k - cum; break; }
                cum += cc;
            }
            s_thr = (unsigned int)bin; s_r = r;
        }
    }
    __syncthreads();
    unsigned int thr = s_thr;
    if ((int)thr < 0) return;                    // k<=0: topk stays 0
    if (blockIdx.x == 0 && t == 0) { g_thr[b] = thr; g_r[b] = s_r; }
    const int chunk = AA / 32;
    size_t base = (size_t)b * AA + (size_t)blockIdx.x * chunk;
    double acc = 0.0;
#pragma unroll 4
    for (int i = t; i < chunk; i += 256) {
        float v = g_mining[base + i];
        unsigned int u = __float_as_uint(v);
        if ((int)u >= 0) {
            unsigned int bin = u >> SH;
            if (bin > thr) acc += (double)v;
            else if (bin == thr) {
                int slot = atomicAdd(&g_ncand[b], 1);
                g_cand[(size_t)b * AA + slot] = v;
            }
        }
    }
    for (int o = 16; o; o >>= 1) acc += __shfl_down_sync(0xffffffffu, acc, o);
    if ((t & 31) == 0) sred[t >> 5] = acc;
    __syncthreads();
    if (t == 0) {
        double tot = 0.0;
        for (int i = 0; i < 8; i++) tot += sred[i];
        if (tot != 0.0) atomicAdd(&g_sumabove[b], tot);
    }
}

// exact refinement (3 passes over thr-bin candidates) + fused final combine
__global__ void __launch_bounds__(256) k_sel2(float* __restrict__ out) {
    int b = blockIdx.x;
    int t = threadIdx.x;
    int r = g_r[b];
    __shared__ unsigned int hc[256];
    __shared__ double hsum[256];
    __shared__ unsigned int s_pref, s_pmask;
    __shared__ int s_r2;
    __shared__ double s_acc;
    __shared__ int s_last;
    if (r == 0) {
        if (t == 0) g_topk_sum[b] = g_sumabove[b];
    } else {
        int n = g_ncand[b];
        unsigned int thr = g_thr[b];
        const float* cand = g_cand + (size_t)b * AA;
        if (t == 0) { s_pref = 0u; s_pmask = 0u; s_r2 = r; s_acc = 0.0; }
        const int shifts[3] = {11, 3, 0};
        const int nbins[3]  = {256, 256, 8};
        for (int p = 0; p < 3; p++) {
            hc[t] = 0; hsum[t] = 0.0;
            __syncthreads();
            unsigned int pref = s_pref, pmask = s_pmask;
            int sh = shifts[p];
            unsigned int wmask = (unsigned)(nbins[p] - 1);
            for (int i = t; i < n; i += 256) {
                float v = cand[i];
                unsigned int u = __float_as_uint(v);
                if ((u & pmask) == pref) {
                    unsigned int idx = (u >> sh) & wmask;
                    atomicAdd(&hc[idx], 1u);
                    atomicAdd(&hsum[idx], (double)v);
                }
            }
            __syncthreads();
            if (t == 0) {
                int rr = s_r2, cum = 0; double sa = 0.0; int bin = nbins[p] - 1;
                for (bin = nbins[p] - 1; bin >= 0; bin--) {
                    int cc = (int)hc[bin];
                    if (cum + cc >= rr) break;
                    cum += cc; sa += hsum[bin];
                }
                s_acc += sa;
                s_r2 = rr - cum;
                s_pref |= (unsigned)bin << sh;
                s_pmask |= wmask << sh;
            }
            __syncthreads();
        }
        if (t == 0) {
            unsigned int thr2 = g_thr[b];
            unsigned int fb = (thr2 << SH) | s_pref;   // exact tie value
            g_topk_sum[b] = g_sumabove[b] + s_acc + (double)s_r2 * (double)__uint_as_float(fb);
        }
    }
    // last-block final combine (O(BB) work only)
    __threadfence();
    if (t == 0) {
        int old = atomicAdd(&g_ctr, 1);
        s_last = (old == BB - 1);
    }
    __syncthreads();
    if (s_last && t == 0) {
        long long np = 0;
        double tk = 0.0;
        for (int bb = 0; bb < BB; bb++) { np += g_num_pos[bb]; tk += g_topk_sum[bb]; }
        double num_pos = (np < 1) ? 1.0 : (double)np;
        double inv = 1.0 / (num_pos * 4.0);
        out[0] = (float)(g_loc_sum * inv);
        out[1] = (float)((g_ce_sum + tk) * inv);
    }
}

extern "C" void kernel_launch(void* const* d_in, const int* in_sizes, int n_in,
                              void* d_out, int out_size) {
    const float* conf    = (const float*)d_in[0];
    const float* pred    = (const float*)d_in[1];
    const float* gts     = (const float*)d_in[2];
    const int*   counts  = (const int*)  d_in[3];
    const float* anchors = (const float*)d_in[4];
    float* out = (float*)d_out;

    static int attr_set = 0;
    if (!attr_set) {
        cudaFuncSetAttribute(k_conf, cudaFuncAttributeMaxDynamicSharedMemorySize,
                             2 * TILE_F * sizeof(float));
        attr_set = 1;
    }

    int initg = (HIST_THIRD + 255) / 256;
    k_init_a<<<initg, 256>>>();
    k_init_b<<<initg, 256>>>();
    k_init_c<<<initg, 256>>>();
    dim3 gm((AA + 255) / 256, BB);
    k_match<<<gm, 256>>>(gts, counts, anchors, pred);   // launch #4 -> profiled
    k_force<<<BB, GG>>>(gts, counts, anchors, pred);
    k_conf<<<(BB * AA) / (CROWS * CT), 128, 2 * TILE_F * sizeof(float)>>>(conf);
    k_hist<<<dim3(32, BB), 256>>>();
    k_collect<<<dim3(32, BB), 256>>>();
    k_sel2<<<BB, 256>>>(out);
}

// round 13
// speedup vs baseline: 4.2640x; 1.0129x over previous
#include <cuda_runtime.h>
#include <math.h>
#include <stdint.h>

#define BB 16
#define AA 65472
#define CC 81
#define GG 50
#define NBIN 4096
#define SH 19

__device__ float  g_best_iou[BB * AA];
__device__ int    g_best_idx[BB * AA];
__device__ int    g_labels[BB * AA];
__device__ float  g_mining[BB * AA];
__device__ float  g_cand[BB * AA];
__device__ unsigned long long g_gt_pack[BB * GG];
__device__ int    g_num_pos[BB];
__device__ int    g_ncand[BB];
__device__ unsigned int g_thr[BB];
__device__ int    g_r[BB];
__device__ double g_sumabove[BB];
__device__ double g_topk_sum[BB];
__device__ double g_loc_sum;
__device__ double g_ce_sum;
__device__ unsigned int g_hist12[BB][NBIN];
__device__ int    g_ctr;

__device__ __forceinline__ float sl1_loss(float4 an, const float* __restrict__ gp, float4 p) {
    float acx = (an.x + an.z) * 0.5f, acy = (an.y + an.w) * 0.5f;
    float aw = an.z - an.x, ah = an.w - an.y;
    float mcx = (gp[0] + gp[2]) * 0.5f, mcy = (gp[1] + gp[3]) * 0.5f;
    float mw = gp[2] - gp[0], mh = gp[3] - gp[1];
    float t0 = (mcx - acx) / (aw * 0.1f);
    float t1 = (mcy - acy) / (ah * 0.1f);
    float t2 = logf(mw / aw + 1e-10f) * 5.0f;
    float t3 = logf(mh / ah + 1e-10f) * 5.0f;
    float n0 = fabsf(p.x - t0), n1 = fabsf(p.y - t1);
    float n2 = fabsf(p.z - t2), n3 = fabsf(p.w - t3);
    const float BETA = 1.0f / 9.0f;
    return (n0 < BETA ? 4.5f * n0 * n0 : n0 - 0.5f * BETA)
         + (n1 < BETA ? 4.5f * n1 * n1 : n1 - 0.5f * BETA)
         + (n2 < BETA ? 4.5f * n2 * n2 : n2 - 0.5f * BETA)
         + (n3 < BETA ? 4.5f * n3 * n3 : n3 - 0.5f * BETA);
}

__device__ __forceinline__ void cp_async16(float* dst, const float4* src) {
    unsigned sa = (unsigned)__cvta_generic_to_shared(dst);
    asm volatile("cp.async.cg.shared.global [%0], [%1], 16;" :: "r"(sa), "l"(src));
}

__global__ void k_init() {                       // 256 blocks x 256 threads
    int i = blockIdx.x * 256 + threadIdx.x;      // 65536 = BB*NBIN
    ((unsigned int*)g_hist12)[i] = 0u;
    if (i < BB * GG) g_gt_pack[i] = 0xFFFFFFFFull;   // iou=0, anchor 0 default
    if (i < BB) {
        g_num_pos[i] = 0; g_ncand[i] = 0; g_r[i] = 0;
        g_topk_sum[i] = 0.0; g_sumabove[i] = 0.0;
    }
    if (i == 0) { g_loc_sum = 0.0; g_ce_sum = 0.0; g_ctr = 0; }
}

// 4-anchor-per-thread match: amortized LDS + 4-way ILP
__global__ void __launch_bounds__(128) k_match(const float* __restrict__ gts,
                                               const int* __restrict__ counts,
                                               const float* __restrict__ anchors,
                                               const float* __restrict__ pred) {
    int b = blockIdx.y;
    int t = threadIdx.x;
    int base = blockIdx.x * 512;                 // 128 blocks cover 65536 >= AA
    __shared__ float4 sbox[GG];
    __shared__ float  sarea[GG];
    __shared__ float  slab[GG];
    __shared__ unsigned long long spack[GG];
    __shared__ double s_loc;
    __shared__ int s_np;
    if (t < GG) {
        const float* gp = gts + ((size_t)b * GG + t) * 5;
        float4 bx = make_float4(gp[0], gp[1], gp[2], gp[3]);
        sbox[t] = bx;
        sarea[t] = (bx.z - bx.x) * (bx.w - bx.y) + 1e-10f;
        slab[t] = gp[4];
        spack[t] = 0ull;
    }
    if (t == 0) { s_loc = 0.0; s_np = 0; }
    __syncthreads();
    int count = counts[b];

    float4 an[4];
    float  areaA[4], bq[4];
    int    bg[4], aidx[4];
#pragma unroll
    for (int k = 0; k < 4; k++) {
        int a = base + k * 128 + t;
        aidx[k] = a;
        float4 x = (a < AA) ? ((const float4*)anchors)[a] : make_float4(0.f, 0.f, 0.f, 0.f);
        an[k] = x;
        areaA[k] = (x.z - x.x) * (x.w - x.y);
        bq[k] = 0.f; bg[k] = 0;
    }

    for (int g = 0; g < count; g++) {
        float4 bx = sbox[g];
        float ar = sarea[g];
        unsigned long long lpk = 0ull;
#pragma unroll
        for (int k = 0; k < 4; k++) {
            float wx = fminf(an[k].z, bx.z) - fmaxf(an[k].x, bx.x);
            float wy = fminf(an[k].w, bx.w) - fmaxf(an[k].y, bx.y);
            wx = fmaxf(wx, 0.f); wy = fmaxf(wy, 0.f);
            float inter = wx * wy;
            float q = __fdividef(inter, areaA[k] + ar - inter);
            if (q > bq[k]) { bq[k] = q; bg[k] = g; }      // first-max (asc g)
            if (inter > 0.f) {
                unsigned long long pk =
                    (((unsigned long long)__float_as_uint(q)) << 32)
                    | (0xFFFFFFFFu - (unsigned)aidx[k]);   // lower anchor wins ties
                if (pk > lpk) lpk = pk;
            }
        }
        if (lpk && lpk > spack[g]) atomicMax(&spack[g], lpk);  // racy read = filter
    }

    float lsum = 0.f;
    int np = 0;
#pragma unroll
    for (int k = 0; k < 4; k++) {
        int a = aidx[k];
        if (a < AA) {
            size_t idx = (size_t)b * AA + a;
            g_best_iou[idx] = bq[k];
            g_best_idx[idx] = bg[k];
            int label = 0;
            if (bq[k] >= 0.5f) {
                label = (int)slab[bg[k]];
                np++;
                const float* gp = gts + ((size_t)b * GG + bg[k]) * 5;
                lsum += sl1_loss(an[k], gp, ((const float4*)pred)[idx]);
            }
            g_labels[idx] = label;
        }
    }
    for (int o = 16; o; o >>= 1) {
        lsum += __shfl_down_sync(0xffffffffu, lsum, o);
        np   += __shfl_down_sync(0xffffffffu, np, o);
    }
    if ((t & 31) == 0 && np) {
        atomicAdd(&s_np, np);
        atomicAdd(&s_loc, (double)lsum);
    }
    __syncthreads();
    if (t == 0 && s_np) {
        atomicAdd(&g_num_pos[b], s_np);
        atomicAdd(&g_loc_sum, s_loc);
    }
    if (t < count && spack[t]) atomicMax(&g_gt_pack[b * GG + t], spack[t]);
}

__global__ void k_force(const float* __restrict__ gts,
                        const int* __restrict__ counts,
                        const float* __restrict__ anchors,
                        const float* __restrict__ pred) {
    int b = blockIdx.x;
    int j = threadIdx.x;
    __shared__ unsigned int sa[GG];
    int count = counts[b];
    unsigned int a = 0;
    if (j < count) {
        unsigned long long pk = g_gt_pack[b * GG + j];
        a = 0xFFFFFFFFu - (unsigned int)(pk & 0xFFFFFFFFull);
        sa[j] = a;
    }
    __syncthreads();
    if (j < count) {
        bool ok = true;                          // duplicate scatter: last j wins
        for (int j2 = j + 1; j2 < count; j2++)
            if (sa[j2] == a) ok = false;
        if (ok) {
            size_t idx = (size_t)b * AA + a;
            float q_old = g_best_iou[idx];
            int g_old = g_best_idx[idx];
            float4 an = ((const float4*)anchors)[a];
            float4 p = ((const float4*)pred)[idx];
            float loc_old = 0.0f;
            if (q_old >= 0.5f)
                loc_old = sl1_loss(an, gts + ((size_t)b * GG + g_old) * 5, p);
            else
                atomicAdd(&g_num_pos[b], 1);
            const float* gp = gts + ((size_t)b * GG + j) * 5;
            float loc_new = sl1_loss(an, gp, p);
            atomicAdd(&g_loc_sum, (double)loc_new - (double)loc_old);
            g_labels[idx] = (int)gp[4];
        }
    }
}

// cp.async double-buffered: 128 threads, 4 tiles of 128 rows per block (R8 shape)
#define CROWS 128
#define CT 4
#define TILE_F (CROWS * CC)                      // 10368 floats
#define TILE_V (TILE_F / 4)                      // 2592 float4
__global__ void __launch_bounds__(128) k_conf(const float* __restrict__ conf) {
    extern __shared__ float s[];                 // 2 * TILE_F floats = 82944 B
    __shared__ double sce[4];
    int t = threadIdx.x;
    size_t tile0 = (size_t)blockIdx.x * CT;
    {   // prologue: async load tile 0 -> buf 0
        const float4* src = (const float4*)conf + tile0 * TILE_V;
        for (int i = t; i < TILE_V; i += 128) cp_async16(s + 4 * i, src + i);
        asm volatile("cp.async.commit_group;");
    }
    double ce_acc = 0.0;
#pragma unroll
    for (int it = 0; it < CT; it++) {
        if (it + 1 < CT) {                       // prefetch next tile
            float* buf = s + ((it + 1) & 1) * TILE_F;
            const float4* src = (const float4*)conf + (tile0 + it + 1) * TILE_V;
            for (int i = t; i < TILE_V; i += 128) cp_async16(buf + 4 * i, src + i);
            asm volatile("cp.async.commit_group;");
            asm volatile("cp.async.wait_group 1;");
        } else {
            asm volatile("cp.async.wait_group 0;");
        }
        size_t rowbase = (tile0 + it) * CROWS;
        int label = g_labels[rowbase + t];
        __syncthreads();                         // tile 'it' visible to all
        const float* row = s + (it & 1) * TILE_F + t * CC;   // stride 81: conflict-free
        float e0 = 0.f, e1 = 0.f, e2 = 0.f, e3 = 0.f;
#pragma unroll
        for (int i = 0; i < 80; i += 4) {
            e0 += __expf(row[i]);
            e1 += __expf(row[i + 1]);
            e2 += __expf(row[i + 2]);
            e3 += __expf(row[i + 3]);
        }
        e0 += __expf(row[80]);
        float lse = __logf((e0 + e1) + (e2 + e3));
        float m;
        if (label > 0) {
            ce_acc += (double)(lse - row[label]);
            m = __int_as_float(0xff800000);      // -inf marker (bit31 set)
        } else {
            m = lse - row[0];                    // > 0 always
        }
        g_mining[rowbase + t] = m;
        __syncthreads();                         // done reading buf before reuse
    }
    float ce = (float)ce_acc;
    for (int o = 16; o; o >>= 1) ce += __shfl_down_sync(0xffffffffu, ce, o);
    if ((t & 31) == 0) sce[t >> 5] = (double)ce;
    __syncthreads();
    if (t == 0) {
        double tot = sce[0] + sce[1] + sce[2] + sce[3];
        if (tot != 0.0) atomicAdd(&g_ce_sum, tot);
    }
}

// distributed 12-bit histogram: 512 blocks, 16KB private smem
__global__ void __launch_bounds__(256) k_hist() {
    __shared__ unsigned int sh[NBIN];
    int b = blockIdx.y;
#pragma unroll
    for (int i = threadIdx.x; i < NBIN; i += 256) sh[i] = 0;
    __syncthreads();
    const int chunk = AA / 32;                   // 2046 exact
    size_t base = (size_t)b * AA + (size_t)blockIdx.x * chunk;
#pragma unroll 4
    for (int i = threadIdx.x; i < chunk; i += 256) {
        unsigned int u = __float_as_uint(g_mining[base + i]);
        if ((int)u >= 0) atomicAdd(&sh[u >> SH], 1u);
    }
    __syncthreads();
#pragma unroll
    for (int i = threadIdx.x; i < NBIN; i += 256) {
        unsigned int c = sh[i];
        if (c) atomicAdd(&g_hist12[b][i], c);
    }
}

// 512 blocks: redundant bin walk -> thr,r ; scan own chunk
__global__ void __launch_bounds__(256) k_collect() {
    __shared__ unsigned int scnt[256];
    __shared__ unsigned int s_thr;
    __shared__ int s_r;
    __shared__ double sred[8];
    int b = blockIdx.y;
    int t = threadIdx.x;
    int np = g_num_pos[b];
    long long kk = 3LL * np;
    int neg = AA - np;
    int k = (kk < (long long)neg) ? (int)kk : neg;
    {
        int lo = NBIN - (t + 1) * 16;            // descending 16-bin chunks
        unsigned int c = 0;
#pragma unroll
        for (int i = 0; i < 16; i++) c += g_hist12[b][lo + i];
        scnt[t] = c;
    }
    __syncthreads();
    if (t == 0) {
        if (k <= 0) { s_thr = 0xFFFFFFFFu; s_r = 0; }
        else {
            int cum = 0, j = 0;
            for (; j < 256; j++) {
                if (cum + (int)scnt[j] >= k) break;
                cum += (int)scnt[j];
            }
            int hi = NBIN - j * 16 - 1;
            int bin = hi, r = k - cum;
            for (int i = 0; i < 16; i++) {
                bin = hi - i;
                int cc = (int)g_hist12[b][bin];
                if (cum + cc >= k) { r = k - cum; break; }
                cum += cc;
            }
            s_thr = (unsigned int)bin; s_r = r;
        }
    }
    __syncthreads();
    unsigned int thr = s_thr;
    if ((int)thr < 0) return;                    // k<=0: topk stays 0
    if (blockIdx.x == 0 && t == 0) { g_thr[b] = thr; g_r[b] = s_r; }
    const int chunk = AA / 32;
    size_t base = (size_t)b * AA + (size_t)blockIdx.x * chunk;
    double acc = 0.0;
#pragma unroll 4
    for (int i = t; i < chunk; i += 256) {
        float v = g_mining[base + i];
        unsigned int u = __float_as_uint(v);
        if ((int)u >= 0) {
            unsigned int bin = u >> SH;
            if (bin > thr) acc += (double)v;
            else if (bin == thr) {
                int slot = atomicAdd(&g_ncand[b], 1);
                g_cand[(size_t)b * AA + slot] = v;
            }
        }
    }
    for (int o = 16; o; o >>= 1) acc += __shfl_down_sync(0xffffffffu, acc, o);
    if ((t & 31) == 0) sred[t >> 5] = acc;
    __syncthreads();
    if (t == 0) {
        double tot = 0.0;
        for (int i = 0; i < 8; i++) tot += sred[i];
        if (tot != 0.0) atomicAdd(&g_sumabove[b], tot);
    }
}

// exact refinement (3 passes over thr-bin candidates) + fused final combine
__global__ void __launch_bounds__(256) k_sel2(float* __restrict__ out) {
    int b = blockIdx.x;
    int t = threadIdx.x;
    int r = g_r[b];
    __shared__ unsigned int hc[256];
    __shared__ double hsum[256];
    __shared__ unsigned int s_pref, s_pmask;
    __shared__ int s_r2;
    __shared__ double s_acc;
    __shared__ int s_last;
    if (r == 0) {
        if (t == 0) g_topk_sum[b] = g_sumabove[b];
    } else {
        int n = g_ncand[b];
        const float* cand = g_cand + (size_t)b * AA;
        if (t == 0) { s_pref = 0u; s_pmask = 0u; s_r2 = r; s_acc = 0.0; }
        const int shifts[3] = {11, 3, 0};
        const int nbins[3]  = {256, 256, 8};
        for (int p = 0; p < 3; p++) {
            hc[t] = 0; hsum[t] = 0.0;
            __syncthreads();
            unsigned int pref = s_pref, pmask = s_pmask;
            int sh = shifts[p];
            unsigned int wmask = (unsigned)(nbins[p] - 1);
            for (int i = t; i < n; i += 256) {
                float v = cand[i];
                unsigned int u = __float_as_uint(v);
                if ((u & pmask) == pref) {
                    unsigned int idx = (u >> sh) & wmask;
                    atomicAdd(&hc[idx], 1u);
                    atomicAdd(&hsum[idx], (double)v);
                }
            }
            __syncthreads();
            if (t == 0) {
                int rr = s_r2, cum = 0; double sa = 0.0; int bin = nbins[p] - 1;
                for (bin = nbins[p] - 1; bin >= 0; bin--) {
                    int cc = (int)hc[bin];
                    if (cum + cc >= rr) break;
                    cum += cc; sa += hsum[bin];
                }
                s_acc += sa;
                s_r2 = rr - cum;
                s_pref |= (unsigned)bin << sh;
                s_pmask |= wmask << sh;
            }
            __syncthreads();
        }
        if (t == 0) {
            unsigned int thr2 = g_thr[b];
            unsigned int fb = (thr2 << SH) | s_pref;   // exact tie value
            g_topk_sum[b] = g_sumabove[b] + s_acc + (double)s_r2 * (double)__uint_as_float(fb);
        }
    }
    // last-block final combine (O(BB) work only)
    __threadfence();
    if (t == 0) {
        int old = atomicAdd(&g_ctr, 1);
        s_last = (old == BB - 1);
    }
    __syncthreads();
    if (s_last && t == 0) {
        long long np = 0;
        double tk = 0.0;
        for (int bb = 0; bb < BB; bb++) { np += g_num_pos[bb]; tk += g_topk_sum[bb]; }
        double num_pos = (np < 1) ? 1.0 : (double)np;
        double inv = 1.0 / (num_pos * 4.0);
        out[0] = (float)(g_loc_sum * inv);
        out[1] = (float)((g_ce_sum + tk) * inv);
    }
}

extern "C" void kernel_launch(void* const* d_in, const int* in_sizes, int n_in,
                              void* d_out, int out_size) {
    const float* conf    = (const float*)d_in[0];
    const float* pred    = (const float*)d_in[1];
    const float* gts     = (const float*)d_in[2];
    const int*   counts  = (const int*)  d_in[3];
    const float* anchors = (const float*)d_in[4];
    float* out = (float*)d_out;

    static int attr_set = 0;
    if (!attr_set) {
        cudaFuncSetAttribute(k_conf, cudaFuncAttributeMaxDynamicSharedMemorySize,
                             2 * TILE_F * sizeof(float));
        attr_set = 1;
    }

    k_init<<<BB * NBIN / 256, 256>>>();
    dim3 gm(128, BB);
    k_match<<<gm, 128>>>(gts, counts, anchors, pred);
    k_force<<<BB, GG>>>(gts, counts, anchors, pred);
    k_conf<<<(BB * AA) / (CROWS * CT), 128, 2 * TILE_F * sizeof(float)>>>(conf);  // #4 profiled
    k_hist<<<dim3(32, BB), 256>>>();
    k_collect<<<dim3(32, BB), 256>>>();
    k_sel2<<<BB, 256>>>(out);
}

// round 14
// speedup vs baseline: 4.3962x; 1.0310x over previous
#include <cuda_runtime.h>
#include <math.h>
#include <stdint.h>

#define BB 16
#define AA 65472
#define CC 81
#define GG 50
#define NBIN 4096
#define SH 19

__device__ float  g_best_iou[BB * AA];
__device__ int    g_best_idx[BB * AA];
__device__ int    g_labels[BB * AA];
__device__ float  g_mining[BB * AA];
__device__ float  g_cand[BB * AA];
__device__ unsigned long long g_gt_pack[BB * GG];
__device__ int    g_num_pos[BB];
__device__ int    g_ncand[BB];
__device__ unsigned int g_thr[BB];
__device__ int    g_r[BB];
__device__ double g_sumabove[BB];
__device__ double g_topk_sum[BB];
__device__ double g_loc_sum;
__device__ double g_ce_sum;
__device__ unsigned int g_hist12[BB][NBIN];
__device__ int    g_ctr;

__device__ __forceinline__ float sl1_loss(float4 an, const float* __restrict__ gp, float4 p) {
    float acx = (an.x + an.z) * 0.5f, acy = (an.y + an.w) * 0.5f;
    float aw = an.z - an.x, ah = an.w - an.y;
    float mcx = (gp[0] + gp[2]) * 0.5f, mcy = (gp[1] + gp[3]) * 0.5f;
    float mw = gp[2] - gp[0], mh = gp[3] - gp[1];
    float t0 = (mcx - acx) / (aw * 0.1f);
    float t1 = (mcy - acy) / (ah * 0.1f);
    float t2 = logf(mw / aw + 1e-10f) * 5.0f;
    float t3 = logf(mh / ah + 1e-10f) * 5.0f;
    float n0 = fabsf(p.x - t0), n1 = fabsf(p.y - t1);
    float n2 = fabsf(p.z - t2), n3 = fabsf(p.w - t3);
    const float BETA = 1.0f / 9.0f;
    return (n0 < BETA ? 4.5f * n0 * n0 : n0 - 0.5f * BETA)
         + (n1 < BETA ? 4.5f * n1 * n1 : n1 - 0.5f * BETA)
         + (n2 < BETA ? 4.5f * n2 * n2 : n2 - 0.5f * BETA)
         + (n3 < BETA ? 4.5f * n3 * n3 : n3 - 0.5f * BETA);
}

__device__ __forceinline__ void cp_async16(float* dst, const float4* src) {
    unsigned sa = (unsigned)__cvta_generic_to_shared(dst);
    asm volatile("cp.async.cg.shared.global [%0], [%1], 16;" :: "r"(sa), "l"(src));
}

__global__ void k_init() {                       // 256 blocks x 256 threads
    int i = blockIdx.x * 256 + threadIdx.x;      // 65536 = BB*NBIN
    ((unsigned int*)g_hist12)[i] = 0u;
    if (i < BB * GG) g_gt_pack[i] = 0xFFFFFFFFull;   // iou=0, anchor 0 default
    if (i < BB) {
        g_num_pos[i] = 0; g_ncand[i] = 0; g_r[i] = 0;
        g_topk_sum[i] = 0.0; g_sumabove[i] = 0.0;
    }
    if (i == 0) { g_loc_sum = 0.0; g_ce_sum = 0.0; g_ctr = 0; }
}

// 4-anchor-per-thread match: amortized LDS + 4-way ILP
__global__ void __launch_bounds__(128) k_match(const float* __restrict__ gts,
                                               const int* __restrict__ counts,
                                               const float* __restrict__ anchors,
                                               const float* __restrict__ pred) {
    int b = blockIdx.y;
    int t = threadIdx.x;
    int base = blockIdx.x * 512;                 // 128 blocks cover 65536 >= AA
    __shared__ float4 sbox[GG];
    __shared__ float  sarea[GG];
    __shared__ float  slab[GG];
    __shared__ unsigned long long spack[GG];
    __shared__ double s_loc;
    __shared__ int s_np;
    if (t < GG) {
        const float* gp = gts + ((size_t)b * GG + t) * 5;
        float4 bx = make_float4(gp[0], gp[1], gp[2], gp[3]);
        sbox[t] = bx;
        sarea[t] = (bx.z - bx.x) * (bx.w - bx.y) + 1e-10f;
        slab[t] = gp[4];
        spack[t] = 0ull;
    }
    if (t == 0) { s_loc = 0.0; s_np = 0; }
    __syncthreads();
    int count = counts[b];

    float4 an[4];
    float  areaA[4], bq[4];
    int    bg[4], aidx[4];
#pragma unroll
    for (int k = 0; k < 4; k++) {
        int a = base + k * 128 + t;
        aidx[k] = a;
        float4 x = (a < AA) ? ((const float4*)anchors)[a] : make_float4(0.f, 0.f, 0.f, 0.f);
        an[k] = x;
        areaA[k] = (x.z - x.x) * (x.w - x.y);
        bq[k] = 0.f; bg[k] = 0;
    }

    for (int g = 0; g < count; g++) {
        float4 bx = sbox[g];
        float ar = sarea[g];
        unsigned long long lpk = 0ull;
#pragma unroll
        for (int k = 0; k < 4; k++) {
            float wx = fminf(an[k].z, bx.z) - fmaxf(an[k].x, bx.x);
            float wy = fminf(an[k].w, bx.w) - fmaxf(an[k].y, bx.y);
            wx = fmaxf(wx, 0.f); wy = fmaxf(wy, 0.f);
            float inter = wx * wy;
            float q = __fdividef(inter, areaA[k] + ar - inter);
            if (q > bq[k]) { bq[k] = q; bg[k] = g; }      // first-max (asc g)
            if (inter > 0.f) {
                unsigned long long pk =
                    (((unsigned long long)__float_as_uint(q)) << 32)
                    | (0xFFFFFFFFu - (unsigned)aidx[k]);   // lower anchor wins ties
                if (pk > lpk) lpk = pk;
            }
        }
        if (lpk && lpk > spack[g]) atomicMax(&spack[g], lpk);  // racy read = filter
    }

    float lsum = 0.f;
    int np = 0;
#pragma unroll
    for (int k = 0; k < 4; k++) {
        int a = aidx[k];
        if (a < AA) {
            size_t idx = (size_t)b * AA + a;
            g_best_iou[idx] = bq[k];
            g_best_idx[idx] = bg[k];
            int label = 0;
            if (bq[k] >= 0.5f) {
                label = (int)slab[bg[k]];
                np++;
                const float* gp = gts + ((size_t)b * GG + bg[k]) * 5;
                lsum += sl1_loss(an[k], gp, ((const float4*)pred)[idx]);
            }
            g_labels[idx] = label;
        }
    }
    for (int o = 16; o; o >>= 1) {
        lsum += __shfl_down_sync(0xffffffffu, lsum, o);
        np   += __shfl_down_sync(0xffffffffu, np, o);
    }
    if ((t & 31) == 0 && np) {
        atomicAdd(&s_np, np);
        atomicAdd(&s_loc, (double)lsum);
    }
    __syncthreads();
    if (t == 0 && s_np) {
        atomicAdd(&g_num_pos[b], s_np);
        atomicAdd(&g_loc_sum, s_loc);
    }
    if (t < count && spack[t]) atomicMax(&g_gt_pack[b * GG + t], spack[t]);
}

__global__ void k_force(const float* __restrict__ gts,
                        const int* __restrict__ counts,
                        const float* __restrict__ anchors,
                        const float* __restrict__ pred) {
    int b = blockIdx.x;
    int j = threadIdx.x;
    __shared__ unsigned int sa[GG];
    int count = counts[b];
    unsigned int a = 0;
    if (j < count) {
        unsigned long long pk = g_gt_pack[b * GG + j];
        a = 0xFFFFFFFFu - (unsigned int)(pk & 0xFFFFFFFFull);
        sa[j] = a;
    }
    __syncthreads();
    if (j < count) {
        bool ok = true;                          // duplicate scatter: last j wins
        for (int j2 = j + 1; j2 < count; j2++)
            if (sa[j2] == a) ok = false;
        if (ok) {
            size_t idx = (size_t)b * AA + a;
            float q_old = g_best_iou[idx];
            int g_old = g_best_idx[idx];
            float4 an = ((const float4*)anchors)[a];
            float4 p = ((const float4*)pred)[idx];
            float loc_old = 0.0f;
            if (q_old >= 0.5f)
                loc_old = sl1_loss(an, gts + ((size_t)b * GG + g_old) * 5, p);
            else
                atomicAdd(&g_num_pos[b], 1);
            const float* gp = gts + ((size_t)b * GG + j) * 5;
            float loc_new = sl1_loss(an, gp, p);
            atomicAdd(&g_loc_sum, (double)loc_new - (double)loc_old);
            g_labels[idx] = (int)gp[4];
        }
    }
}

// label-FREE conf pass: mining = lse - row[0] for every row (runs concurrent with match)
#define CROWS 128
#define CT 4
#define TILE_F (CROWS * CC)                      // 10368 floats
#define TILE_V (TILE_F / 4)                      // 2592 float4
__global__ void __launch_bounds__(128) k_conf(const float* __restrict__ conf) {
    extern __shared__ float s[];                 // 2 * TILE_F floats = 82944 B
    int t = threadIdx.x;
    size_t tile0 = (size_t)blockIdx.x * CT;
    {   // prologue: async load tile 0 -> buf 0
        const float4* src = (const float4*)conf + tile0 * TILE_V;
        for (int i = t; i < TILE_V; i += 128) cp_async16(s + 4 * i, src + i);
        asm volatile("cp.async.commit_group;");
    }
#pragma unroll
    for (int it = 0; it < CT; it++) {
        if (it + 1 < CT) {                       // prefetch next tile
            float* buf = s + ((it + 1) & 1) * TILE_F;
            const float4* src = (const float4*)conf + (tile0 + it + 1) * TILE_V;
            for (int i = t; i < TILE_V; i += 128) cp_async16(buf + 4 * i, src + i);
            asm volatile("cp.async.commit_group;");
            asm volatile("cp.async.wait_group 1;");
        } else {
            asm volatile("cp.async.wait_group 0;");
        }
        __syncthreads();                         // tile 'it' visible to all
        const float* row = s + (it & 1) * TILE_F + t * CC;   // stride 81: conflict-free
        float e0 = 0.f, e1 = 0.f, e2 = 0.f, e3 = 0.f;
#pragma unroll
        for (int i = 0; i < 80; i += 4) {
            e0 += __expf(row[i]);
            e1 += __expf(row[i + 1]);
            e2 += __expf(row[i + 2]);
            e3 += __expf(row[i + 3]);
        }
        e0 += __expf(row[80]);
        float lse = __logf((e0 + e1) + (e2 + e3));
        g_mining[(tile0 + it) * CROWS + t] = lse - row[0];
        __syncthreads();                         // done reading buf before reuse
    }
}

// fixup positives: ce = (mining + c0) - conf[row*81+label]; mining <- -inf
__global__ void __launch_bounds__(256) k_fix(const float* __restrict__ conf) {
    size_t i = (size_t)blockIdx.x * 256 + threadIdx.x;   // 4092 blocks exact
    __shared__ double sce[8];
    int label = g_labels[i];
    float ce = 0.f;
    if (label > 0) {
        float m = g_mining[i];
        float c0 = conf[i * CC];
        float cl = conf[i * CC + label];
        ce = (m + c0) - cl;                      // == lse - row[label] (±1ulp)
        g_mining[i] = __int_as_float(0xff800000);
    }
    for (int o = 16; o; o >>= 1) ce += __shfl_down_sync(0xffffffffu, ce, o);
    if ((threadIdx.x & 31) == 0) sce[threadIdx.x >> 5] = (double)ce;
    __syncthreads();
    if (threadIdx.x == 0) {
        double tot = 0.0;
        for (int j = 0; j < 8; j++) tot += sce[j];
        if (tot != 0.0) atomicAdd(&g_ce_sum, tot);
    }
}

// distributed 12-bit histogram: 512 blocks, 16KB private smem
__global__ void __launch_bounds__(256) k_hist() {
    __shared__ unsigned int sh[NBIN];
    int b = blockIdx.y;
#pragma unroll
    for (int i = threadIdx.x; i < NBIN; i += 256) sh[i] = 0;
    __syncthreads();
    const int chunk = AA / 32;                   // 2046 exact
    size_t base = (size_t)b * AA + (size_t)blockIdx.x * chunk;
#pragma unroll 4
    for (int i = threadIdx.x; i < chunk; i += 256) {
        unsigned int u = __float_as_uint(g_mining[base + i]);
        if ((int)u >= 0) atomicAdd(&sh[u >> SH], 1u);
    }
    __syncthreads();
#pragma unroll
    for (int i = threadIdx.x; i < NBIN; i += 256) {
        unsigned int c = sh[i];
        if (c) atomicAdd(&g_hist12[b][i], c);
    }
}

// 512 blocks: redundant bin walk -> thr,r ; scan own chunk
__global__ void __launch_bounds__(256) k_collect() {
    __shared__ unsigned int scnt[256];
    __shared__ unsigned int s_thr;
    __shared__ int s_r;
    __shared__ double sred[8];
    int b = blockIdx.y;
    int t = threadIdx.x;
    int np = g_num_pos[b];
    long long kk = 3LL * np;
    int neg = AA - np;
    int k = (kk < (long long)neg) ? (int)kk : neg;
    {
        int lo = NBIN - (t + 1) * 16;            // descending 16-bin chunks
        unsigned int c = 0;
#pragma unroll
        for (int i = 0; i < 16; i++) c += g_hist12[b][lo + i];
        scnt[t] = c;
    }
    __syncthreads();
    if (t == 0) {
        if (k <= 0) { s_thr = 0xFFFFFFFFu; s_r = 0; }
        else {
            int cum = 0, j = 0;
            for (; j < 256; j++) {
                if (cum + (int)scnt[j] >= k) break;
                cum += (int)scnt[j];
            }
            int hi = NBIN - j * 16 - 1;
            int bin = hi, r = k - cum;
            for (int i = 0; i < 16; i++) {
                bin = hi - i;
                int cc = (int)g_hist12[b][bin];
                if (cum + cc >= k) { r = k - cum; break; }
                cum += cc;
            }
            s_thr = (unsigned int)bin; s_r = r;
        }
    }
    __syncthreads();
    unsigned int thr = s_thr;
    if ((int)thr < 0) return;                    // k<=0: topk stays 0
    if (blockIdx.x == 0 && t == 0) { g_thr[b] = thr; g_r[b] = s_r; }
    const int chunk = AA / 32;
    size_t base = (size_t)b * AA + (size_t)blockIdx.x * chunk;
    double acc = 0.0;
#pragma unroll 4
    for (int i = t; i < chunk; i += 256) {
        float v = g_mining[base + i];
        unsigned int u = __float_as_uint(v);
        if ((int)u >= 0) {
            unsigned int bin = u >> SH;
            if (bin > thr) acc += (double)v;
            else if (bin == thr) {
                int slot = atomicAdd(&g_ncand[b], 1);
                g_cand[(size_t)b * AA + slot] = v;
            }
        }
    }
    for (int o = 16; o; o >>= 1) acc += __shfl_down_sync(0xffffffffu, acc, o);
    if ((t & 31) == 0) sred[t >> 5] = acc;
    __syncthreads();
    if (t == 0) {
        double tot = 0.0;
        for (int i = 0; i < 8; i++) tot += sred[i];
        if (tot != 0.0) atomicAdd(&g_sumabove[b], tot);
    }
}

// exact refinement (3 passes over thr-bin candidates) + fused final combine
__global__ void __launch_bounds__(256) k_sel2(float* __restrict__ out) {
    int b = blockIdx.x;
    int t = threadIdx.x;
    int r = g_r[b];
    __shared__ unsigned int hc[256];
    __shared__ double hsum[256];
    __shared__ unsigned int s_pref, s_pmask;
    __shared__ int s_r2;
    __shared__ double s_acc;
    __shared__ int s_last;
    if (r == 0) {
        if (t == 0) g_topk_sum[b] = g_sumabove[b];
    } else {
        int n = g_ncand[b];
        const float* cand = g_cand + (size_t)b * AA;
        if (t == 0) { s_pref = 0u; s_pmask = 0u; s_r2 = r; s_acc = 0.0; }
        const int shifts[3] = {11, 3, 0};
        const int nbins[3]  = {256, 256, 8};
        for (int p = 0; p < 3; p++) {
            hc[t] = 0; hsum[t] = 0.0;
            __syncthreads();
            unsigned int pref = s_pref, pmask = s_pmask;
            int sh = shifts[p];
            unsigned int wmask = (unsigned)(nbins[p] - 1);
            for (int i = t; i < n; i += 256) {
                float v = cand[i];
                unsigned int u = __float_as_uint(v);
                if ((u & pmask) == pref) {
                    unsigned int idx = (u >> sh) & wmask;
                    atomicAdd(&hc[idx], 1u);
                    atomicAdd(&hsum[idx], (double)v);
                }
            }
            __syncthreads();
            if (t == 0) {
                int rr = s_r2, cum = 0; double sa = 0.0; int bin = nbins[p] - 1;
                for (bin = nbins[p] - 1; bin >= 0; bin--) {
                    int cc = (int)hc[bin];
                    if (cum + cc >= rr) break;
                    cum += cc; sa += hsum[bin];
                }
                s_acc += sa;
                s_r2 = rr - cum;
                s_pref |= (unsigned)bin << sh;
                s_pmask |= wmask << sh;
            }
            __syncthreads();
        }
        if (t == 0) {
            unsigned int thr2 = g_thr[b];
            unsigned int fb = (thr2 << SH) | s_pref;   // exact tie value
            g_topk_sum[b] = g_sumabove[b] + s_acc + (double)s_r2 * (double)__uint_as_float(fb);
        }
    }
    // last-block final combine (O(BB) work only)
    __threadfence();
    if (t == 0) {
        int old = atomicAdd(&g_ctr, 1);
        s_last = (old == BB - 1);
    }
    __syncthreads();
    if (s_last && t == 0) {
        long long np = 0;
        double tk = 0.0;
        for (int bb = 0; bb < BB; bb++) { np += g_num_pos[bb]; tk += g_topk_sum[bb]; }
        double num_pos = (np < 1) ? 1.0 : (double)np;
        double inv = 1.0 / (num_pos * 4.0);
        out[0] = (float)(g_loc_sum * inv);
        out[1] = (float)((g_ce_sum + tk) * inv);
    }
}

extern "C" void kernel_launch(void* const* d_in, const int* in_sizes, int n_in,
                              void* d_out, int out_size) {
    const float* conf    = (const float*)d_in[0];
    const float* pred    = (const float*)d_in[1];
    const float* gts     = (const float*)d_in[2];
    const int*   counts  = (const int*)  d_in[3];
    const float* anchors = (const float*)d_in[4];
    float* out = (float*)d_out;

    static cudaStream_t s2;
    static cudaEvent_t ev_fork, ev_join;
    static int once = 0;
    if (!once) {
        cudaStreamCreateWithFlags(&s2, cudaStreamNonBlocking);
        cudaEventCreateWithFlags(&ev_fork, cudaEventDisableTiming);
        cudaEventCreateWithFlags(&ev_join, cudaEventDisableTiming);
        cudaFuncSetAttribute(k_conf, cudaFuncAttributeMaxDynamicSharedMemorySize,
                             2 * TILE_F * sizeof(float));
        once = 1;
    }

    k_init<<<BB * NBIN / 256, 256>>>();
    cudaEventRecord(ev_fork, 0);
    cudaStreamWaitEvent(s2, ev_fork, 0);
    // branch B (stream s2): compute-bound matching
    dim3 gm(128, BB);
    k_match<<<gm, 128, 0, s2>>>(gts, counts, anchors, pred);
    k_force<<<BB, GG, 0, s2>>>(gts, counts, anchors, pred);
    cudaEventRecord(ev_join, s2);
    // branch A (default stream): DRAM-bound conf pass, label-free
    k_conf<<<(BB * AA) / (CROWS * CT), 128, 2 * TILE_F * sizeof(float)>>>(conf);
    // join
    cudaStreamWaitEvent(0, ev_join, 0);
    k_fix<<<(BB * AA) / 256, 256>>>(conf);
    k_hist<<<dim3(32, BB), 256>>>();
    k_collect<<<dim3(32, BB), 256>>>();
    k_sel2<<<BB, 256>>>(out);
}

// round 15
// speedup vs baseline: 4.4400x; 1.0100x over previous
#include <cuda_runtime.h>
#include <math.h>
#include <stdint.h>

#define BB 16
#define AA 65472
#define CC 81
#define GG 50
#define NBIN 4096
#define SH 19

__device__ float  g_best_iou[BB * AA];
__device__ int    g_best_idx[BB * AA];
__device__ int    g_labels[BB * AA];
__device__ float  g_mining[BB * AA];
__device__ float  g_cand[BB * AA];
__device__ unsigned long long g_gt_pack[BB * GG];
__device__ int    g_num_pos[BB];
__device__ int    g_ncand[BB];
__device__ double g_sumabove[BB];
__device__ double g_topk_sum[BB];
__device__ double g_loc_sum;
__device__ double g_ce_sum;
__device__ unsigned int g_hist12[BB][NBIN];
__device__ int    g_bctr[BB];
__device__ int    g_ctr;

__device__ __forceinline__ float sl1_loss(float4 an, const float* __restrict__ gp, float4 p) {
    float acx = (an.x + an.z) * 0.5f, acy = (an.y + an.w) * 0.5f;
    float aw = an.z - an.x, ah = an.w - an.y;
    float mcx = (gp[0] + gp[2]) * 0.5f, mcy = (gp[1] + gp[3]) * 0.5f;
    float mw = gp[2] - gp[0], mh = gp[3] - gp[1];
    float t0 = (mcx - acx) / (aw * 0.1f);
    float t1 = (mcy - acy) / (ah * 0.1f);
    float t2 = logf(mw / aw + 1e-10f) * 5.0f;
    float t3 = logf(mh / ah + 1e-10f) * 5.0f;
    float n0 = fabsf(p.x - t0), n1 = fabsf(p.y - t1);
    float n2 = fabsf(p.z - t2), n3 = fabsf(p.w - t3);
    const float BETA = 1.0f / 9.0f;
    return (n0 < BETA ? 4.5f * n0 * n0 : n0 - 0.5f * BETA)
         + (n1 < BETA ? 4.5f * n1 * n1 : n1 - 0.5f * BETA)
         + (n2 < BETA ? 4.5f * n2 * n2 : n2 - 0.5f * BETA)
         + (n3 < BETA ? 4.5f * n3 * n3 : n3 - 0.5f * BETA);
}

__device__ __forceinline__ void cp_async16(float* dst, const float4* src) {
    unsigned sa = (unsigned)__cvta_generic_to_shared(dst);
    asm volatile("cp.async.cg.shared.global [%0], [%1], 16;" :: "r"(sa), "l"(src));
}

__global__ void k_init() {                       // 256 blocks x 256 threads
    int i = blockIdx.x * 256 + threadIdx.x;      // 65536 = BB*NBIN
    ((unsigned int*)g_hist12)[i] = 0u;
    if (i < BB * GG) g_gt_pack[i] = 0xFFFFFFFFull;   // iou=0, anchor 0 default
    if (i < BB) {
        g_num_pos[i] = 0; g_ncand[i] = 0; g_bctr[i] = 0;
        g_topk_sum[i] = 0.0; g_sumabove[i] = 0.0;
    }
    if (i == 0) { g_loc_sum = 0.0; g_ce_sum = 0.0; g_ctr = 0; }
}

// 4-anchor-per-thread match: amortized LDS + 4-way ILP
__global__ void __launch_bounds__(128) k_match(const float* __restrict__ gts,
                                               const int* __restrict__ counts,
                                               const float* __restrict__ anchors,
                                               const float* __restrict__ pred) {
    int b = blockIdx.y;
    int t = threadIdx.x;
    int base = blockIdx.x * 512;                 // 128 blocks cover 65536 >= AA
    __shared__ float4 sbox[GG];
    __shared__ float  sarea[GG];
    __shared__ float  slab[GG];
    __shared__ unsigned long long spack[GG];
    __shared__ double s_loc;
    __shared__ int s_np;
    if (t < GG) {
        const float* gp = gts + ((size_t)b * GG + t) * 5;
        float4 bx = make_float4(gp[0], gp[1], gp[2], gp[3]);
        sbox[t] = bx;
        sarea[t] = (bx.z - bx.x) * (bx.w - bx.y) + 1e-10f;
        slab[t] = gp[4];
        spack[t] = 0ull;
    }
    if (t == 0) { s_loc = 0.0; s_np = 0; }
    __syncthreads();
    int count = counts[b];

    float4 an[4];
    float  areaA[4], bq[4];
    int    bg[4], aidx[4];
#pragma unroll
    for (int k = 0; k < 4; k++) {
        int a = base + k * 128 + t;
        aidx[k] = a;
        float4 x = (a < AA) ? ((const float4*)anchors)[a] : make_float4(0.f, 0.f, 0.f, 0.f);
        an[k] = x;
        areaA[k] = (x.z - x.x) * (x.w - x.y);
        bq[k] = 0.f; bg[k] = 0;
    }

    for (int g = 0; g < count; g++) {
        float4 bx = sbox[g];
        float ar = sarea[g];
        unsigned long long lpk = 0ull;
#pragma unroll
        for (int k = 0; k < 4; k++) {
            float wx = fminf(an[k].z, bx.z) - fmaxf(an[k].x, bx.x);
            float wy = fminf(an[k].w, bx.w) - fmaxf(an[k].y, bx.y);
            wx = fmaxf(wx, 0.f); wy = fmaxf(wy, 0.f);
            float inter = wx * wy;
            float q = __fdividef(inter, areaA[k] + ar - inter);
            if (q > bq[k]) { bq[k] = q; bg[k] = g; }      // first-max (asc g)
            if (inter > 0.f) {
                unsigned long long pk =
                    (((unsigned long long)__float_as_uint(q)) << 32)
                    | (0xFFFFFFFFu - (unsigned)aidx[k]);   // lower anchor wins ties
                if (pk > lpk) lpk = pk;
            }
        }
        if (lpk && lpk > spack[g]) atomicMax(&spack[g], lpk);  // racy read = filter
    }

    float lsum = 0.f;
    int np = 0;
#pragma unroll
    for (int k = 0; k < 4; k++) {
        int a = aidx[k];
        if (a < AA) {
            size_t idx = (size_t)b * AA + a;
            g_best_iou[idx] = bq[k];
            g_best_idx[idx] = bg[k];
            int label = 0;
            if (bq[k] >= 0.5f) {
                label = (int)slab[bg[k]];
                np++;
                const float* gp = gts + ((size_t)b * GG + bg[k]) * 5;
                lsum += sl1_loss(an[k], gp, ((const float4*)pred)[idx]);
            }
            g_labels[idx] = label;
        }
    }
    for (int o = 16; o; o >>= 1) {
        lsum += __shfl_down_sync(0xffffffffu, lsum, o);
        np   += __shfl_down_sync(0xffffffffu, np, o);
    }
    if ((t & 31) == 0 && np) {
        atomicAdd(&s_np, np);
        atomicAdd(&s_loc, (double)lsum);
    }
    __syncthreads();
    if (t == 0 && s_np) {
        atomicAdd(&g_num_pos[b], s_np);
        atomicAdd(&g_loc_sum, s_loc);
    }
    if (t < count && spack[t]) atomicMax(&g_gt_pack[b * GG + t], spack[t]);
}

__global__ void k_force(const float* __restrict__ gts,
                        const int* __restrict__ counts,
                        const float* __restrict__ anchors,
                        const float* __restrict__ pred) {
    int b = blockIdx.x;
    int j = threadIdx.x;
    __shared__ unsigned int sa[GG];
    int count = counts[b];
    unsigned int a = 0;
    if (j < count) {
        unsigned long long pk = g_gt_pack[b * GG + j];
        a = 0xFFFFFFFFu - (unsigned int)(pk & 0xFFFFFFFFull);
        sa[j] = a;
    }
    __syncthreads();
    if (j < count) {
        bool ok = true;                          // duplicate scatter: last j wins
        for (int j2 = j + 1; j2 < count; j2++)
            if (sa[j2] == a) ok = false;
        if (ok) {
            size_t idx = (size_t)b * AA + a;
            float q_old = g_best_iou[idx];
            int g_old = g_best_idx[idx];
            float4 an = ((const float4*)anchors)[a];
            float4 p = ((const float4*)pred)[idx];
            float loc_old = 0.0f;
            if (q_old >= 0.5f)
                loc_old = sl1_loss(an, gts + ((size_t)b * GG + g_old) * 5, p);
            else
                atomicAdd(&g_num_pos[b], 1);
            const float* gp = gts + ((size_t)b * GG + j) * 5;
            float loc_new = sl1_loss(an, gp, p);
            atomicAdd(&g_loc_sum, (double)loc_new - (double)loc_old);
            g_labels[idx] = (int)gp[4];
        }
    }
}

// label-FREE conf pass: mining = lse - row[0] for every row (concurrent with match)
#define CROWS 128
#define CT 4
#define TILE_F (CROWS * CC)                      // 10368 floats
#define TILE_V (TILE_F / 4)                      // 2592 float4
__global__ void __launch_bounds__(128) k_conf(const float* __restrict__ conf) {
    extern __shared__ float s[];                 // 2 * TILE_F floats = 82944 B
    int t = threadIdx.x;
    size_t tile0 = (size_t)blockIdx.x * CT;
    {   // prologue: async load tile 0 -> buf 0
        const float4* src = (const float4*)conf + tile0 * TILE_V;
        for (int i = t; i < TILE_V; i += 128) cp_async16(s + 4 * i, src + i);
        asm volatile("cp.async.commit_group;");
    }
#pragma unroll
    for (int it = 0; it < CT; it++) {
        if (it + 1 < CT) {                       // prefetch next tile
            float* buf = s + ((it + 1) & 1) * TILE_F;
            const float4* src = (const float4*)conf + (tile0 + it + 1) * TILE_V;
            for (int i = t; i < TILE_V; i += 128) cp_async16(buf + 4 * i, src + i);
            asm volatile("cp.async.commit_group;");
            asm volatile("cp.async.wait_group 1;");
        } else {
            asm volatile("cp.async.wait_group 0;");
        }
        __syncthreads();                         // tile 'it' visible to all
        const float* row = s + (it & 1) * TILE_F + t * CC;   // stride 81: conflict-free
        float e0 = 0.f, e1 = 0.f, e2 = 0.f, e3 = 0.f;
#pragma unroll
        for (int i = 0; i < 80; i += 4) {
            e0 += __expf(row[i]);
            e1 += __expf(row[i + 1]);
            e2 += __expf(row[i + 2]);
            e3 += __expf(row[i + 3]);
        }
        e0 += __expf(row[80]);
        float lse = __logf((e0 + e1) + (e2 + e3));
        g_mining[(tile0 + it) * CROWS + t] = lse - row[0];
        __syncthreads();                         // done reading buf before reuse
    }
}

// fused fix + histogram: one 4MB pass; positives fixed (ce, -inf), negatives binned
__global__ void __launch_bounds__(256) k_fixhist(const float* __restrict__ conf) {
    __shared__ unsigned int sh[NBIN];
    __shared__ double sce[8];
    int b = blockIdx.y;
    int t = threadIdx.x;
#pragma unroll
    for (int i = t; i < NBIN; i += 256) sh[i] = 0;
    __syncthreads();
    const int chunk = AA / 32;                   // 2046 exact
    size_t base = (size_t)b * AA + (size_t)blockIdx.x * chunk;
    float ce = 0.f;
#pragma unroll 4
    for (int i = t; i < chunk; i += 256) {
        size_t idx = base + i;
        int label = g_labels[idx];
        float m = g_mining[idx];
        if (label > 0) {
            float c0 = conf[idx * CC];
            float cl = conf[idx * CC + label];
            ce += (m + c0) - cl;                 // == lse - row[label] (±1ulp)
            g_mining[idx] = __int_as_float(0xff800000);
        } else {
            atomicAdd(&sh[__float_as_uint(m) >> SH], 1u);
        }
    }
    for (int o = 16; o; o >>= 1) ce += __shfl_down_sync(0xffffffffu, ce, o);
    if ((t & 31) == 0) sce[t >> 5] = (double)ce;
    __syncthreads();
    if (t == 0) {
        double tot = 0.0;
        for (int j = 0; j < 8; j++) tot += sce[j];
        if (tot != 0.0) atomicAdd(&g_ce_sum, tot);
    }
#pragma unroll
    for (int i = t; i < NBIN; i += 256) {
        unsigned int c = sh[i];
        if (c) atomicAdd(&g_hist12[b][i], c);
    }
}

// fused collect + per-batch refinement + final combine (two-level last-block)
__global__ void __launch_bounds__(256) k_collectsel(float* __restrict__ out) {
    __shared__ unsigned int scnt[256];
    __shared__ unsigned int s_thr;
    __shared__ int s_r;
    __shared__ double sred[8];
    __shared__ int s_lastb, s_lastg;
    __shared__ unsigned int hc[256];
    __shared__ double hsum[256];
    __shared__ unsigned int s_pref, s_pmask;
    __shared__ int s_r2;
    __shared__ double s_acc;
    int b = blockIdx.y;
    int t = threadIdx.x;
    int np = g_num_pos[b];
    long long kk = 3LL * np;
    int neg = AA - np;
    int k = (kk < (long long)neg) ? (int)kk : neg;
    {
        int lo = NBIN - (t + 1) * 16;            // descending 16-bin chunks
        unsigned int c = 0;
#pragma unroll
        for (int i = 0; i < 16; i++) c += g_hist12[b][lo + i];
        scnt[t] = c;
    }
    __syncthreads();
    if (t == 0) {
        if (k <= 0) { s_thr = 0xFFFFFFFFu; s_r = 0; }
        else {
            int cum = 0, j = 0;
            for (; j < 256; j++) {
                if (cum + (int)scnt[j] >= k) break;
                cum += (int)scnt[j];
            }
            int hi = NBIN - j * 16 - 1;
            int bin = hi, r = k - cum;
            for (int i = 0; i < 16; i++) {
                bin = hi - i;
                int cc = (int)g_hist12[b][bin];
                if (cum + cc >= k) { r = k - cum; break; }
                cum += cc;
            }
            s_thr = (unsigned int)bin; s_r = r;
        }
    }
    __syncthreads();
    unsigned int thr = s_thr;
    int r = s_r;
    if ((int)thr >= 0) {                         // k > 0: scan own chunk
        const int chunk = AA / 32;
        size_t base = (size_t)b * AA + (size_t)blockIdx.x * chunk;
        double acc = 0.0;
#pragma unroll 4
        for (int i = t; i < chunk; i += 256) {
            float v = g_mining[base + i];
            unsigned int u = __float_as_uint(v);
            if ((int)u >= 0) {
                unsigned int bin = u >> SH;
                if (bin > thr) acc += (double)v;
                else if (bin == thr) {
                    int slot = atomicAdd(&g_ncand[b], 1);
                    g_cand[(size_t)b * AA + slot] = v;
                }
            }
        }
        for (int o = 16; o; o >>= 1) acc += __shfl_down_sync(0xffffffffu, acc, o);
        if ((t & 31) == 0) sred[t >> 5] = acc;
        __syncthreads();
        if (t == 0) {
            double tot = 0.0;
            for (int i = 0; i < 8; i++) tot += sred[i];
            if (tot != 0.0) atomicAdd(&g_sumabove[b], tot);
        }
    }
    // level-1: last block of this batch does exact refinement (O(cands))
    __threadfence();
    if (t == 0) {
        int old = atomicAdd(&g_bctr[b], 1);
        s_lastb = (old == (int)gridDim.x - 1);
    }
    __syncthreads();
    if (s_lastb) {
        if (r > 0) {
            int n = g_ncand[b];
            const float* cand = g_cand + (size_t)b * AA;
            if (t == 0) { s_pref = 0u; s_pmask = 0u; s_r2 = r; s_acc = 0.0; }
            const int shifts[3] = {11, 3, 0};
            const int nbins[3]  = {256, 256, 8};
            for (int p = 0; p < 3; p++) {
                hc[t] = 0; hsum[t] = 0.0;
                __syncthreads();
                unsigned int pref = s_pref, pmask = s_pmask;
                int sh2 = shifts[p];
                unsigned int wmask = (unsigned)(nbins[p] - 1);
                for (int i = t; i < n; i += 256) {
                    float v = cand[i];
                    unsigned int u = __float_as_uint(v);
                    if ((u & pmask) == pref) {
                        unsigned int idx = (u >> sh2) & wmask;
                        atomicAdd(&hc[idx], 1u);
                        atomicAdd(&hsum[idx], (double)v);
                    }
                }
                __syncthreads();
                if (t == 0) {
                    int rr = s_r2, cum = 0; double sa = 0.0; int bin = nbins[p] - 1;
                    for (bin = nbins[p] - 1; bin >= 0; bin--) {
                        int cc = (int)hc[bin];
                        if (cum + cc >= rr) break;
                        cum += cc; sa += hsum[bin];
                    }
                    s_acc += sa;
                    s_r2 = rr - cum;
                    s_pref |= (unsigned)bin << sh2;
                    s_pmask |= wmask << sh2;
                }
                __syncthreads();
            }
            if (t == 0) {
                unsigned int fb = (thr << SH) | s_pref;    // exact tie value
                g_topk_sum[b] = g_sumabove[b] + s_acc
                              + (double)s_r2 * (double)__uint_as_float(fb);
            }
        } else if (t == 0) {
            g_topk_sum[b] = g_sumabove[b];
        }
        // level-2: very last batch finisher combines (O(BB))
        __threadfence();
        if (t == 0) {
            int old = atomicAdd(&g_ctr, 1);
            s_lastg = (old == BB - 1);
        }
        __syncthreads();
        if (s_lastg && t == 0) {
            long long npt = 0;
            double tk = 0.0;
            for (int bb = 0; bb < BB; bb++) { npt += g_num_pos[bb]; tk += g_topk_sum[bb]; }
            double num_pos = (npt < 1) ? 1.0 : (double)npt;
            double inv = 1.0 / (num_pos * 4.0);
            out[0] = (float)(g_loc_sum * inv);
            out[1] = (float)((g_ce_sum + tk) * inv);
        }
    }
}

extern "C" void kernel_launch(void* const* d_in, const int* in_sizes, int n_in,
                              void* d_out, int out_size) {
    const float* conf    = (const float*)d_in[0];
    const float* pred    = (const float*)d_in[1];
    const float* gts     = (const float*)d_in[2];
    const int*   counts  = (const int*)  d_in[3];
    const float* anchors = (const float*)d_in[4];
    float* out = (float*)d_out;

    static cudaStream_t s2;
    static cudaEvent_t ev_fork, ev_join;
    static int once = 0;
    if (!once) {
        cudaStreamCreateWithFlags(&s2, cudaStreamNonBlocking);
        cudaEventCreateWithFlags(&ev_fork, cudaEventDisableTiming);
        cudaEventCreateWithFlags(&ev_join, cudaEventDisableTiming);
        cudaFuncSetAttribute(k_conf, cudaFuncAttributeMaxDynamicSharedMemorySize,
                             2 * TILE_F * sizeof(float));
        once = 1;
    }

    k_init<<<BB * NBIN / 256, 256>>>();
    cudaEventRecord(ev_fork, 0);
    cudaStreamWaitEvent(s2, ev_fork, 0);
    // branch B (stream s2): compute-bound matching
    dim3 gm(128, BB);
    k_match<<<gm, 128, 0, s2>>>(gts, counts, anchors, pred);
    k_force<<<BB, GG, 0, s2>>>(gts, counts, anchors, pred);
    cudaEventRecord(ev_join, s2);
    // branch A (default stream): DRAM-bound conf pass, label-free
    k_conf<<<(BB * AA) / (CROWS * CT), 128, 2 * TILE_F * sizeof(float)>>>(conf);
    // join
    cudaStreamWaitEvent(0, ev_join, 0);
    k_fixhist<<<dim3(32, BB), 256>>>(conf);
    k_collectsel<<<dim3(32, BB), 256>>>(out);
}